// round 12
// baseline (speedup 1.0000x reference)
#include <cuda_runtime.h>
#include <cuda_fp16.h>
#include <float.h>
#include <math.h>
#include <stdint.h>

// Problem constants
#define B_    8
#define NPTS  8192
#define NS    2048
#define D1    128
#define D2    256
#define C1    384      // D1 + D2
#define C2    256
#define C3    128
#define MTOT  (B_ * NPTS)   // 65536
#define GRIDX (MTOT / 128)  // 512 column blocks per GEMM

// ---------------------------------------------------------------------------
// Scratch (static device globals — no allocations allowed)
// ---------------------------------------------------------------------------
// Unified GEMM1 B operand, half2 k-pairs [cpair][m]: rows 0..63 = skip,
// rows 64..191 = interpolated features. 48 MB.
__device__ __align__(16) uint32_t g_BP1[(size_t)(C1 / 2) * MTOT];
__device__ float  g_h1[(size_t)C2 * MTOT];       // 64 MB GEMM1 out (pre-BN) [c][m]
__device__ float  g_h2[(size_t)C3 * MTOT];       // 32 MB GEMM2 out (pre-BN) [c][m]
__device__ float  g_sfT[(size_t)B_ * NS * D2];   // 16 MB sfeat transposed [b][s][c]
__device__ float4 g_w[MTOT];                     // per-point 3-NN weights
__device__ int4   g_i[MTOT];                     // per-point 3-NN indices
__device__ float2 g_ss1[C2];                     // BN1 (scale, shift)
__device__ float2 g_ss2[C3];                     // BN2 (scale, shift)
__device__ __align__(16) __half g_W1h[C2 * C1];  // fp16 weights, row-major
__device__ __align__(16) __half g_W2h[C3 * C2];
// per-block BN partial stats (deterministic two-stage reduction, no atomics)
__device__ float g_psA[C2 * GRIDX], g_pqA[C2 * GRIDX];
__device__ float g_psB[C3 * GRIDX], g_pqB[C3 * GRIDX];

__device__ __forceinline__ void mma16816(float* d, const uint32_t* a, const uint32_t* b) {
    asm volatile(
        "mma.sync.aligned.m16n8k16.row.col.f32.f16.f16.f32 "
        "{%0,%1,%2,%3}, {%4,%5,%6,%7}, {%8,%9}, {%0,%1,%2,%3};\n"
        : "+f"(d[0]), "+f"(d[1]), "+f"(d[2]), "+f"(d[3])
        : "r"(a[0]), "r"(a[1]), "r"(a[2]), "r"(a[3]), "r"(b[0]), "r"(b[1]));
}

__device__ __forceinline__ void cp_async16(uint32_t smem_addr, const void* gptr) {
    asm volatile("cp.async.ca.shared.global [%0], [%1], 16;\n"
                 :: "r"(smem_addr), "l"(gptr));
}
#define CP_COMMIT()  asm volatile("cp.async.commit_group;\n")
#define CP_WAIT(N)   asm volatile("cp.async.wait_group %0;\n" :: "n"(N))

// ---------------------------------------------------------------------------
// Kernel 1 (launch #1): fused prep — weight fp16 convert + skip pack +
// sfeat transpose. All three are independent; dispatched by blockIdx range.
//   [0, 384)        : W1/W2 -> fp16
//   [384, 4480)     : pack skip -> g_BP1 rows 0..63
//   [4480, 8576)    : transpose sfeat -> g_sfT
// ---------------------------------------------------------------------------
#define PREP_W_BLOCKS   384
#define PREP_PS_BLOCKS  4096   // (MTOT/1024=64) x (D1/2=64)
#define PREP_TR_BLOCKS  4096   // (NS/32=64) x (D2/32=8) x B_=8
#define PREP_TOTAL      (PREP_W_BLOCKS + PREP_PS_BLOCKS + PREP_TR_BLOCKS)

__global__ void __launch_bounds__(256) prep_all_kernel(
    const float* __restrict__ W1, const float* __restrict__ W2,
    const float* __restrict__ skip, const float* __restrict__ sfeat)
{
    const int bid = blockIdx.x;
    const int tid = threadIdx.x;

    if (bid < PREP_W_BLOCKS) {
        int i = bid * 256 + tid;
        if (i < C2 * C1) g_W1h[i] = __float2half_rn(W1[i]);
        if (i < C3 * C2) g_W2h[i] = __float2half_rn(W2[i]);
        return;
    }
    if (bid < PREP_W_BLOCKS + PREP_PS_BLOCKS) {
        int pb = bid - PREP_W_BLOCKS;
        int cp = pb >> 6;                        // 0..63
        int m0 = ((pb & 63) * 256 + tid) * 4;
        int b  = m0 / NPTS;
        int n  = m0 % NPTS;
        const float* r0 = skip + ((size_t)b * D1 + 2 * cp)     * NPTS + n;
        const float* r1 = skip + ((size_t)b * D1 + 2 * cp + 1) * NPTS + n;
        float4 v0 = *(const float4*)r0;
        float4 v1 = *(const float4*)r1;
        uint32_t p[4];
        const float* x0 = &v0.x; const float* x1 = &v1.x;
        #pragma unroll
        for (int e = 0; e < 4; e++) {
            __half2 h = __floats2half2_rn(x0[e], x1[e]);
            p[e] = *reinterpret_cast<uint32_t*>(&h);
        }
        *(uint4*)&g_BP1[(size_t)cp * MTOT + m0] = *(uint4*)p;
        return;
    }
    {
        __shared__ float tile[32][33];
        int tb = bid - PREP_W_BLOCKS - PREP_PS_BLOCKS;
        int s0 = (tb & 63) * 32;
        int c0 = ((tb >> 6) & 7) * 32;
        int b  = tb >> 9;
        int tx = tid & 31;
        int ty = tid >> 5;                       // 0..7

        #pragma unroll
        for (int r = 0; r < 32; r += 8)
            tile[ty + r][tx] = sfeat[((size_t)b * D2 + c0 + ty + r) * NS + s0 + tx];
        __syncthreads();
        #pragma unroll
        for (int r = 0; r < 32; r += 8)
            g_sfT[((size_t)b * NS + s0 + ty + r) * D2 + c0 + tx] = tile[tx][ty + r];
    }
}

// ---------------------------------------------------------------------------
// Kernel 2 (launch #2): 3-NN search, 4 points per thread.
//   128 threads/block, 512 points/block, 128 blocks.
// ---------------------------------------------------------------------------
#define KP 4
__global__ void __launch_bounds__(128) knn_kernel(
    const float* __restrict__ pp,     // [B,3,N]
    const float* __restrict__ spp)    // [B,3,S]
{
    __shared__ float4 ssmp[NS];       // 32 KB

    const int b   = blockIdx.x >> 4;           // 16 blocks per batch
    const int n0  = (blockIdx.x & 15) << 9;    // 512 points per block
    const int tid = threadIdx.x;

    const float* sb = spp + (size_t)b * 3 * NS;
    for (int s = tid; s < NS; s += 128) {
        float x = sb[s], y = sb[s + NS], z = sb[s + 2 * NS];
        ssmp[s] = make_float4(x, y, z, fmaf(x, x, fmaf(y, y, z * z)));
    }
    __syncthreads();

    const float* pb = pp + (size_t)b * 3 * NPTS;
    float px[KP], py[KP], pz[KP];
    float d0[KP], d1[KP], d2[KP];
    int   i0[KP], i1[KP], i2[KP];
    #pragma unroll
    for (int p = 0; p < KP; p++) {
        int n = n0 + tid + p * 128;
        px[p] = pb[n]; py[p] = pb[n + NPTS]; pz[p] = pb[n + 2 * NPTS];
        d0[p] = d1[p] = d2[p] = FLT_MAX;
        i0[p] = i1[p] = i2[p] = 0;
    }

    #pragma unroll 2
    for (int j = 0; j < NS; j++) {
        float4 q = ssmp[j];
        #pragma unroll
        for (int p = 0; p < KP; p++) {
            float sc = fmaf(-2.0f, fmaf(px[p], q.x, fmaf(py[p], q.y, pz[p] * q.z)), q.w);
            if (sc < d2[p]) {
                if (sc < d1[p]) {
                    d2[p] = d1[p]; i2[p] = i1[p];
                    if (sc < d0[p]) { d1[p] = d0[p]; i1[p] = i0[p]; d0[p] = sc; i0[p] = j; }
                    else            { d1[p] = sc; i1[p] = j; }
                } else { d2[p] = sc; i2[p] = j; }
            }
        }
    }

    #pragma unroll
    for (int p = 0; p < KP; p++) {
        int n = n0 + tid + p * 128;
        const float p2 = fmaf(px[p], px[p], fmaf(py[p], py[p], pz[p] * pz[p]));
        float a0 = 1.0f / ((d0[p] + p2) + 1e-8f);
        float a1 = 1.0f / ((d1[p] + p2) + 1e-8f);
        float a2 = 1.0f / ((d2[p] + p2) + 1e-8f);
        float inv = 1.0f / (a0 + a1 + a2);
        g_w[b * NPTS + n] = make_float4(a0 * inv, a1 * inv, a2 * inv, 0.0f);
        g_i[b * NPTS + n] = make_int4(i0[p], i1[p], i2[p], 0);
    }
}

// ---------------------------------------------------------------------------
// Kernel 3 (launch #3): interpolation -> g_BP1 rows 64..191 (half2 packed)
// ---------------------------------------------------------------------------
__global__ void __launch_bounds__(256) interp_kernel()
{
    __shared__ float  st[D2][33];
    __shared__ float4 sw[32];
    __shared__ int4   si[32];

    const int m0  = blockIdx.x * 32;
    const int b   = m0 / NPTS;
    const int tid = threadIdx.x;

    if (tid < 32) { sw[tid] = g_w[m0 + tid]; si[tid] = g_i[m0 + tid]; }
    __syncthreads();

    const float* fT = g_sfT + (size_t)b * NS * D2;
    #pragma unroll 8
    for (int p = 0; p < 32; p++) {
        float4 w = sw[p];
        int4   ii = si[p];
        float v = fmaf(w.x, __ldg(fT + (size_t)ii.x * D2 + tid),
                  fmaf(w.y, __ldg(fT + (size_t)ii.y * D2 + tid),
                       w.z * __ldg(fT + (size_t)ii.z * D2 + tid)));
        st[tid][p] = v;
    }
    __syncthreads();

    const int cpb = tid >> 3;         // 0..31
    const int j   = (tid & 7) << 2;   // 0,4,...,28
    #pragma unroll
    for (int r = 0; r < 4; r++) {
        int cp = r * 32 + cpb;        // 0..127
        uint32_t v[4];
        #pragma unroll
        for (int e = 0; e < 4; e++) {
            __half2 h = __floats2half2_rn(st[2 * cp][j + e], st[2 * cp + 1][j + e]);
            v[e] = *reinterpret_cast<uint32_t*>(&h);
        }
        *(uint4*)&g_BP1[(size_t)(64 + cp) * MTOT + m0 + j] = *(uint4*)v;
    }
}

// ---------------------------------------------------------------------------
// Shared MMA compute / epilogue fragments
// ---------------------------------------------------------------------------
#define MMA_COMPUTE(ASBUF, BSBUF)                                             \
{                                                                             \
    uint32_t bf[4][2];                                                        \
    _Pragma("unroll")                                                         \
    for (int nt = 0; nt < 4; nt++) {                                          \
        int n = wn * 32 + nt * 8 + g;                                         \
        bf[nt][0] = (BSBUF)[t * 128 + (n ^ (t << 3))];                        \
        bf[nt][1] = (BSBUF)[(t + 4) * 128 + (n ^ ((t + 4) << 3))];            \
    }                                                                         \
    _Pragma("unroll")                                                         \
    for (int mt = 0; mt < 4; mt++) {                                          \
        int r = wm * 64 + mt * 16 + g;                                        \
        uint32_t ah[4];                                                       \
        ah[0] = (ASBUF)[r * 8 + t];                                           \
        ah[1] = (ASBUF)[(r + 8) * 8 + t];                                     \
        ah[2] = (ASBUF)[r * 8 + t + 4];                                       \
        ah[3] = (ASBUF)[(r + 8) * 8 + t + 4];                                 \
        _Pragma("unroll")                                                     \
        for (int nt = 0; nt < 4; nt++)                                        \
            mma16816(acc[mt][nt], ah, bf[nt]);                                \
    }                                                                         \
}

#define MMA_EPILOGUE(DST, PSUM, PSQ, SS_SMEM, SQ_SMEM)                        \
{                                                                             \
    _Pragma("unroll")                                                         \
    for (int mt = 0; mt < 4; mt++) {                                          \
        _Pragma("unroll")                                                     \
        for (int nt = 0; nt < 4; nt++) {                                      \
            int row = i0 + wm * 64 + mt * 16 + g;                             \
            int col = j0 + wn * 32 + nt * 8 + 2 * t;                          \
            *(float2*)&(DST)[(size_t)row * MTOT + col] =                      \
                make_float2(acc[mt][nt][0], acc[mt][nt][1]);                  \
            *(float2*)&(DST)[(size_t)(row + 8) * MTOT + col] =                \
                make_float2(acc[mt][nt][2], acc[mt][nt][3]);                  \
        }                                                                     \
    }                                                                         \
    __syncthreads();                                                          \
    float* Ssum = (SS_SMEM);                                                  \
    float* Ssq  = (SQ_SMEM);                                                  \
    const int ci = wn * 4 + t;                                                \
    _Pragma("unroll")                                                         \
    for (int mt = 0; mt < 4; mt++) {                                          \
        int r0 = wm * 64 + mt * 16 + g;                                       \
        float s0 = 0.f, q0 = 0.f, s1 = 0.f, q1 = 0.f;                         \
        _Pragma("unroll")                                                     \
        for (int nt = 0; nt < 4; nt++) {                                      \
            float e0 = acc[mt][nt][0], e1 = acc[mt][nt][1];                   \
            float e2 = acc[mt][nt][2], e3 = acc[mt][nt][3];                   \
            s0 += e0 + e1;  q0 += e0 * e0 + e1 * e1;                          \
            s1 += e2 + e3;  q1 += e2 * e2 + e3 * e3;                          \
        }                                                                     \
        Ssum[ci * 128 + r0]     = s0;  Ssq[ci * 128 + r0]     = q0;           \
        Ssum[ci * 128 + r0 + 8] = s1;  Ssq[ci * 128 + r0 + 8] = q1;           \
    }                                                                         \
    __syncthreads();                                                          \
    if (tid < 128) {                                                          \
        float s = 0.f;                                                        \
        _Pragma("unroll")                                                     \
        for (int c = 0; c < 16; c++) s += Ssum[c * 128 + tid];                \
        (PSUM)[(size_t)(i0 + tid) * GRIDX + blockIdx.x] = s;                  \
    } else {                                                                  \
        int r = tid - 128;                                                    \
        float q = 0.f;                                                        \
        _Pragma("unroll")                                                     \
        for (int c = 0; c < 16; c++) q += Ssq[c * 128 + r];                   \
        (PSQ)[(size_t)(i0 + r) * GRIDX + blockIdx.x] = q;                     \
    }                                                                         \
}

// ---------------------------------------------------------------------------
// Kernel 4 (launch #4 — PROFILED): GEMM1, fp16 mma, 4-stage cp.async.
//   H1 = W1 @ [skip ; interp], K=384 (24 k-steps). Byte-identical to R9.
// ---------------------------------------------------------------------------
__global__ void __launch_bounds__(256) gemm1_kernel()
{
    __shared__ uint32_t As[4][128 * 8];   // [m][kpair]        4 KB/stage
    __shared__ uint32_t Bs[4][8 * 128];   // [kpair][n ^ swz]  4 KB/stage

    const int tid  = threadIdx.x;
    const int lane = tid & 31;
    const int wid  = tid >> 5;
    const int wm   = wid >> 2;
    const int wn   = wid & 3;
    const int g    = lane >> 2;
    const int t    = lane & 3;

    const int j0 = blockIdx.x * 128;
    const int i0 = blockIdx.y * 128;

    const int arow = tid >> 1;
    const int akh  = tid & 1;
    const int brp  = tid >> 5;
    const int bc0  = lane * 4;

    const uint32_t a_dst0 = (uint32_t)__cvta_generic_to_shared(&As[0][arow * 8 + akh * 4]);
    const uint32_t b_dst0 = (uint32_t)__cvta_generic_to_shared(&Bs[0][brp * 128 + (bc0 ^ (brp << 3))]);
    const __half*   a_src0 = g_W1h + (size_t)(i0 + arow) * C1 + akh * 8;
    const uint32_t* b_src0 = g_BP1 + (size_t)brp * MTOT + j0 + bc0;

    float acc[4][4][4];
    #pragma unroll
    for (int mt = 0; mt < 4; mt++)
        #pragma unroll
        for (int nt = 0; nt < 4; nt++)
            #pragma unroll
            for (int e = 0; e < 4; e++) acc[mt][nt][e] = 0.0f;

    #define G1_ISSUE(step)                                                    \
    {                                                                         \
        int s_ = (step) & 3;                                                  \
        cp_async16(a_dst0 + s_ * 4096, a_src0 + (step) * 16);                 \
        cp_async16(b_dst0 + s_ * 4096, b_src0 + (size_t)(step) * 8 * MTOT);   \
        CP_COMMIT();                                                          \
    }

    G1_ISSUE(0); G1_ISSUE(1); G1_ISSUE(2);

    #pragma unroll 1
    for (int i = 0; i < 21; i++) {
        CP_WAIT(2);
        __syncthreads();
        G1_ISSUE(i + 3);
        MMA_COMPUTE(As[i & 3], Bs[i & 3]);
    }
    CP_WAIT(2); __syncthreads(); MMA_COMPUTE(As[21 & 3], Bs[21 & 3]);
    CP_WAIT(1); __syncthreads(); MMA_COMPUTE(As[22 & 3], Bs[22 & 3]);
    CP_WAIT(0); __syncthreads(); MMA_COMPUTE(As[23 & 3], Bs[23 & 3]);

    MMA_EPILOGUE(g_h1, g_psA, g_pqA, (float*)As, (float*)Bs);
    #undef G1_ISSUE
}

// ---------------------------------------------------------------------------
// Kernel 5: GEMM2 — proven HMMA 2-stage path. H2 = W2 @ relu(BN1(H1)).
// ---------------------------------------------------------------------------
__global__ void __launch_bounds__(256, 2) gemm2_kernel()
{
    __shared__ uint32_t As[2][128 * 8];
    __shared__ uint32_t Bs[2][8 * 128];

    const int tid  = threadIdx.x;
    const int lane = tid & 31;
    const int wid  = tid >> 5;
    const int wm   = wid >> 2;
    const int wn   = wid & 3;
    const int g    = lane >> 2;
    const int t    = lane & 3;

    const int j0 = blockIdx.x * 128;
    const int i0 = blockIdx.y * 128;

    const int arow = tid >> 1;
    const int akh  = tid & 1;
    const int brp  = tid >> 5;
    const int bc0  = lane * 4;

    float acc[4][4][4];
    #pragma unroll
    for (int mt = 0; mt < 4; mt++)
        #pragma unroll
        for (int nt = 0; nt < 4; nt++)
            #pragma unroll
            for (int e = 0; e < 4; e++) acc[mt][nt][e] = 0.0f;

    uint4 ra;
    uint32_t pB[4];

    #define G2_LDG(kt)                                                        \
    {                                                                         \
        ra = *(const uint4*)(g_W2h + (size_t)(i0 + arow) * C2 + (kt) + akh * 8); \
        int k0 = (kt) + brp * 2;                                              \
        const float* s0 = g_h1 + (size_t)k0 * MTOT + j0 + bc0;                \
        float4 rb0 = *(const float4*)s0;                                      \
        float4 rb1 = *(const float4*)(s0 + MTOT);                             \
        float2 q0 = g_ss1[k0], q1 = g_ss1[k0 + 1];                            \
        const float* x0 = &rb0.x; const float* x1 = &rb1.x;                   \
        _Pragma("unroll")                                                     \
        for (int e = 0; e < 4; e++) {                                         \
            float u0 = fmaxf(fmaf(x0[e], q0.x, q0.y), 0.0f);                  \
            float u1 = fmaxf(fmaf(x1[e], q1.x, q1.y), 0.0f);                  \
            __half2 h = __floats2half2_rn(u0, u1);                            \
            pB[e] = *reinterpret_cast<uint32_t*>(&h);                         \
        }                                                                     \
    }

    #define G2_STS(buf)                                                       \
    {                                                                         \
        *(uint4*)&As[buf][arow * 8 + akh * 4] = ra;                           \
        int col = bc0 ^ (brp << 3);                                           \
        *(uint4*)&Bs[buf][brp * 128 + col] = *(uint4*)pB;                     \
    }

    G2_LDG(0);
    G2_STS(0);
    __syncthreads();

    int buf = 0;
    for (int kt = 16; kt < C2; kt += 16) {
        G2_LDG(kt);
        MMA_COMPUTE(As[buf], Bs[buf]);
        G2_STS(buf ^ 1);
        __syncthreads();
        buf ^= 1;
    }
    MMA_COMPUTE(As[buf], Bs[buf]);

    MMA_EPILOGUE(g_h2, g_psB, g_pqB, (float*)As, (float*)Bs);
    #undef G2_LDG
    #undef G2_STS
}

// ---------------------------------------------------------------------------
// Kernel 6: reduce per-block partials -> per-channel (scale, shift).
// ---------------------------------------------------------------------------
__global__ void __launch_bounds__(256) bn_reduce_kernel(
    const float* __restrict__ g, const float* __restrict__ beta, int which)
{
    const int c   = blockIdx.x;
    const int tid = threadIdx.x;
    const float* ps = (which == 1) ? g_psA : g_psB;
    const float* pq = (which == 1) ? g_pqA : g_pqB;

    double s = (double)ps[(size_t)c * GRIDX + tid] + (double)ps[(size_t)c * GRIDX + tid + 256];
    double q = (double)pq[(size_t)c * GRIDX + tid] + (double)pq[(size_t)c * GRIDX + tid + 256];

    __shared__ double r1[256], r2[256];
    r1[tid] = s;  r2[tid] = q;
    __syncthreads();
    for (int o = 128; o > 0; o >>= 1) {
        if (tid < o) { r1[tid] += r1[tid + o]; r2[tid] += r2[tid + o]; }
        __syncthreads();
    }
    if (tid == 0) {
        double mean = r1[0] / (double)MTOT;
        double var  = r2[0] / (double)MTOT - mean * mean;
        double rs   = 1.0 / sqrt(var + 1e-5);
        float scale = (float)((double)g[c] * rs);
        float shift = (float)((double)beta[c] - mean * (double)g[c] * rs);
        if (which == 1) g_ss1[c] = make_float2(scale, shift);
        else            g_ss2[c] = make_float2(scale, shift);
    }
}

// ---------------------------------------------------------------------------
// Kernel 7: final BN2 + ReLU + layout transform [c][b*N+n] -> [b][c][n]
// ---------------------------------------------------------------------------
__global__ void __launch_bounds__(256) bn_out_kernel(float* __restrict__ out)
{
    size_t f = (size_t)blockIdx.x * blockDim.x + threadIdx.x;
    size_t e = f * 4;
    int c = (int)(e / MTOT);
    int m = (int)(e % MTOT);
    int b = m / NPTS;
    int n = m % NPTS;

    float4 v = ((const float4*)g_h2)[f];
    float2 ss = g_ss2[c];
    v.x = fmaxf(fmaf(v.x, ss.x, ss.y), 0.0f);
    v.y = fmaxf(fmaf(v.y, ss.x, ss.y), 0.0f);
    v.z = fmaxf(fmaf(v.z, ss.x, ss.y), 0.0f);
    v.w = fmaxf(fmaf(v.w, ss.x, ss.y), 0.0f);
    *(float4*)(out + ((size_t)b * C3 + c) * NPTS + n) = v;
}

// ---------------------------------------------------------------------------
// Launcher — gemm1 is deliberately the 4th launch (ncu captures launch #4)
// ---------------------------------------------------------------------------
extern "C" void kernel_launch(void* const* d_in, const int* in_sizes, int n_in,
                              void* d_out, int out_size)
{
    const float* pp    = (const float*)d_in[0];
    const float* spp   = (const float*)d_in[1];
    const float* skip  = (const float*)d_in[2];
    const float* sfeat = (const float*)d_in[3];
    const float* W1    = (const float*)d_in[4];
    // d_in[5] = b1 (cancels inside BN)
    const float* g1    = (const float*)d_in[6];
    const float* be1   = (const float*)d_in[7];
    const float* W2    = (const float*)d_in[8];
    // d_in[9] = b2 (cancels inside BN)
    const float* g2    = (const float*)d_in[10];
    const float* be2   = (const float*)d_in[11];
    float* out = (float*)d_out;

    // #1: all independent preprocessing fused
    prep_all_kernel<<<PREP_TOTAL, 256>>>(W1, W2, skip, sfeat);

    // #2: 3-NN (4 points/thread)
    knn_kernel<<<B_ * (NPTS / 512), 128>>>(pp, spp);

    // #3: interpolation -> g_BP1 rows 64..191
    interp_kernel<<<MTOT / 32, 256>>>();

    // #4 (PROFILED): GEMM1 (+BN1 partials): H1 = W1 @ [skip ; interp]
    {
        dim3 grid(GRIDX, C2 / 128);
        gemm1_kernel<<<grid, 256>>>();
    }
    bn_reduce_kernel<<<C2, 256>>>(g1, be1, 1);

    // GEMM2 (+BN2 partials): H2 = W2 @ relu(BN1(H1))
    {
        dim3 grid(GRIDX, C3 / 128);
        gemm2_kernel<<<grid, 256>>>();
    }
    bn_reduce_kernel<<<C3, 256>>>(g2, be2, 2);

    bn_out_kernel<<<(C3 * MTOT / 4) / 256, 256>>>(out);
}

// round 13
// speedup vs baseline: 1.4051x; 1.4051x over previous
#include <cuda_runtime.h>
#include <cuda_fp16.h>
#include <float.h>
#include <math.h>
#include <stdint.h>

// Problem constants
#define B_    8
#define NPTS  8192
#define NS    2048
#define D1    128
#define D2    256
#define C1    384      // D1 + D2
#define C2    256
#define C3    128
#define MTOT  (B_ * NPTS)   // 65536
#define GRIDX (MTOT / 128)  // 512 (BN partial stride; GEMM2 grid)
#define G1GX  (MTOT / 256)  // 256 (GEMM1 column blocks, BN=256)

// ---------------------------------------------------------------------------
// Scratch (static device globals — no allocations allowed)
// ---------------------------------------------------------------------------
__device__ __align__(16) uint32_t g_BP1[(size_t)(C1 / 2) * MTOT]; // 48 MB packed B
__device__ float  g_h1[(size_t)C2 * MTOT];       // 64 MB GEMM1 out (pre-BN) [c][m]
__device__ float  g_h2[(size_t)C3 * MTOT];       // 32 MB GEMM2 out (pre-BN) [c][m]
__device__ float  g_sfT[(size_t)B_ * NS * D2];   // 16 MB sfeat transposed [b][s][c]
__device__ float4 g_w[MTOT];                     // per-point 3-NN weights
__device__ int4   g_i[MTOT];                     // per-point 3-NN indices
__device__ float2 g_ss1[C2];                     // BN1 (scale, shift)
__device__ float2 g_ss2[C3];                     // BN2 (scale, shift)
__device__ __align__(16) __half g_W1h[C2 * C1];  // fp16 weights, row-major
__device__ __align__(16) __half g_W2h[C3 * C2];
// per-block BN partials (deterministic reduction; unwritten tail stays 0)
__device__ float g_psA[C2 * GRIDX], g_pqA[C2 * GRIDX];
__device__ float g_psB[C3 * GRIDX], g_pqB[C3 * GRIDX];

__device__ __forceinline__ void mma16816(float* d, const uint32_t* a, const uint32_t* b) {
    asm volatile(
        "mma.sync.aligned.m16n8k16.row.col.f32.f16.f16.f32 "
        "{%0,%1,%2,%3}, {%4,%5,%6,%7}, {%8,%9}, {%0,%1,%2,%3};\n"
        : "+f"(d[0]), "+f"(d[1]), "+f"(d[2]), "+f"(d[3])
        : "r"(a[0]), "r"(a[1]), "r"(a[2]), "r"(a[3]), "r"(b[0]), "r"(b[1]));
}

__device__ __forceinline__ void cp_async16(uint32_t smem_addr, const void* gptr) {
    asm volatile("cp.async.ca.shared.global [%0], [%1], 16;\n"
                 :: "r"(smem_addr), "l"(gptr));
}
#define CP_COMMIT()  asm volatile("cp.async.commit_group;\n")
#define CP_WAIT(N)   asm volatile("cp.async.wait_group %0;\n" :: "n"(N))

// ---------------------------------------------------------------------------
// Kernel 1 (launch #1): fused prep — weights->fp16, skip pack, sfeat transpose
// ---------------------------------------------------------------------------
#define PREP_W_BLOCKS   384
#define PREP_PS_BLOCKS  4096
#define PREP_TR_BLOCKS  4096
#define PREP_TOTAL      (PREP_W_BLOCKS + PREP_PS_BLOCKS + PREP_TR_BLOCKS)

__global__ void __launch_bounds__(256) prep_all_kernel(
    const float* __restrict__ W1, const float* __restrict__ W2,
    const float* __restrict__ skip, const float* __restrict__ sfeat)
{
    const int bid = blockIdx.x;
    const int tid = threadIdx.x;

    if (bid < PREP_W_BLOCKS) {
        int i = bid * 256 + tid;
        if (i < C2 * C1) g_W1h[i] = __float2half_rn(W1[i]);
        if (i < C3 * C2) g_W2h[i] = __float2half_rn(W2[i]);
        return;
    }
    if (bid < PREP_W_BLOCKS + PREP_PS_BLOCKS) {
        int pb = bid - PREP_W_BLOCKS;
        int cp = pb >> 6;
        int m0 = ((pb & 63) * 256 + tid) * 4;
        int b  = m0 / NPTS;
        int n  = m0 % NPTS;
        const float* r0 = skip + ((size_t)b * D1 + 2 * cp)     * NPTS + n;
        const float* r1 = skip + ((size_t)b * D1 + 2 * cp + 1) * NPTS + n;
        float4 v0 = *(const float4*)r0;
        float4 v1 = *(const float4*)r1;
        uint32_t p[4];
        const float* x0 = &v0.x; const float* x1 = &v1.x;
        #pragma unroll
        for (int e = 0; e < 4; e++) {
            __half2 h = __floats2half2_rn(x0[e], x1[e]);
            p[e] = *reinterpret_cast<uint32_t*>(&h);
        }
        *(uint4*)&g_BP1[(size_t)cp * MTOT + m0] = *(uint4*)p;
        return;
    }
    {
        __shared__ float tile[32][33];
        int tb = bid - PREP_W_BLOCKS - PREP_PS_BLOCKS;
        int s0 = (tb & 63) * 32;
        int c0 = ((tb >> 6) & 7) * 32;
        int b  = tb >> 9;
        int tx = tid & 31;
        int ty = tid >> 5;

        #pragma unroll
        for (int r = 0; r < 32; r += 8)
            tile[ty + r][tx] = sfeat[((size_t)b * D2 + c0 + ty + r) * NS + s0 + tx];
        __syncthreads();
        #pragma unroll
        for (int r = 0; r < 32; r += 8)
            g_sfT[((size_t)b * NS + s0 + ty + r) * D2 + c0 + tx] = tile[tx][ty + r];
    }
}

// ---------------------------------------------------------------------------
// Kernel 2 (launch #2): 3-NN search — proven R9 config: 2 pts/thread,
//   256 blocks x 128 threads (multi-block/SM occupancy hides FSETP latency).
// ---------------------------------------------------------------------------
__global__ void __launch_bounds__(128) knn_kernel(
    const float* __restrict__ pp, const float* __restrict__ spp)
{
    __shared__ float4 ssmp[NS];

    const int b   = blockIdx.x >> 5;
    const int n0  = (blockIdx.x & 31) << 8;
    const int tid = threadIdx.x;

    const float* sb = spp + (size_t)b * 3 * NS;
    for (int s = tid; s < NS; s += 128) {
        float x = sb[s], y = sb[s + NS], z = sb[s + 2 * NS];
        ssmp[s] = make_float4(x, y, z, fmaf(x, x, fmaf(y, y, z * z)));
    }
    __syncthreads();

    const int nA = n0 + tid, nB = nA + 128;
    const float* pb = pp + (size_t)b * 3 * NPTS;
    const float ax = pb[nA], ay = pb[nA + NPTS], az = pb[nA + 2 * NPTS];
    const float bx = pb[nB], by = pb[nB + NPTS], bz = pb[nB + 2 * NPTS];

    float ad0 = FLT_MAX, ad1 = FLT_MAX, ad2 = FLT_MAX;
    float bd0 = FLT_MAX, bd1 = FLT_MAX, bd2 = FLT_MAX;
    int   ai0 = 0, ai1 = 0, ai2 = 0, bi0 = 0, bi1 = 0, bi2 = 0;

    #pragma unroll 4
    for (int j = 0; j < NS; j++) {
        float4 q  = ssmp[j];
        float sA = fmaf(-2.0f, fmaf(ax, q.x, fmaf(ay, q.y, az * q.z)), q.w);
        float sB = fmaf(-2.0f, fmaf(bx, q.x, fmaf(by, q.y, bz * q.z)), q.w);
        if (sA < ad2) {
            if (sA < ad1) {
                ad2 = ad1; ai2 = ai1;
                if (sA < ad0) { ad1 = ad0; ai1 = ai0; ad0 = sA; ai0 = j; }
                else          { ad1 = sA; ai1 = j; }
            } else { ad2 = sA; ai2 = j; }
        }
        if (sB < bd2) {
            if (sB < bd1) {
                bd2 = bd1; bi2 = bi1;
                if (sB < bd0) { bd1 = bd0; bi1 = bi0; bd0 = sB; bi0 = j; }
                else          { bd1 = sB; bi1 = j; }
            } else { bd2 = sB; bi2 = j; }
        }
    }

    {
        const float p2 = fmaf(ax, ax, fmaf(ay, ay, az * az));
        float a0 = 1.0f / ((ad0 + p2) + 1e-8f);
        float a1 = 1.0f / ((ad1 + p2) + 1e-8f);
        float a2 = 1.0f / ((ad2 + p2) + 1e-8f);
        float inv = 1.0f / (a0 + a1 + a2);
        g_w[b * NPTS + nA] = make_float4(a0 * inv, a1 * inv, a2 * inv, 0.0f);
        g_i[b * NPTS + nA] = make_int4(ai0, ai1, ai2, 0);
    }
    {
        const float p2 = fmaf(bx, bx, fmaf(by, by, bz * bz));
        float a0 = 1.0f / ((bd0 + p2) + 1e-8f);
        float a1 = 1.0f / ((bd1 + p2) + 1e-8f);
        float a2 = 1.0f / ((bd2 + p2) + 1e-8f);
        float inv = 1.0f / (a0 + a1 + a2);
        g_w[b * NPTS + nB] = make_float4(a0 * inv, a1 * inv, a2 * inv, 0.0f);
        g_i[b * NPTS + nB] = make_int4(bi0, bi1, bi2, 0);
    }
}

// ---------------------------------------------------------------------------
// Kernel 3 (launch #3): interpolation -> g_BP1 rows 64..191 (half2 packed)
// ---------------------------------------------------------------------------
__global__ void __launch_bounds__(256) interp_kernel()
{
    __shared__ float  st[D2][33];
    __shared__ float4 sw[32];
    __shared__ int4   si[32];

    const int m0  = blockIdx.x * 32;
    const int b   = m0 / NPTS;
    const int tid = threadIdx.x;

    if (tid < 32) { sw[tid] = g_w[m0 + tid]; si[tid] = g_i[m0 + tid]; }
    __syncthreads();

    const float* fT = g_sfT + (size_t)b * NS * D2;
    #pragma unroll 8
    for (int p = 0; p < 32; p++) {
        float4 w = sw[p];
        int4   ii = si[p];
        float v = fmaf(w.x, __ldg(fT + (size_t)ii.x * D2 + tid),
                  fmaf(w.y, __ldg(fT + (size_t)ii.y * D2 + tid),
                       w.z * __ldg(fT + (size_t)ii.z * D2 + tid)));
        st[tid][p] = v;
    }
    __syncthreads();

    const int cpb = tid >> 3;
    const int j   = (tid & 7) << 2;
    #pragma unroll
    for (int r = 0; r < 4; r++) {
        int cp = r * 32 + cpb;
        uint32_t v[4];
        #pragma unroll
        for (int e = 0; e < 4; e++) {
            __half2 h = __floats2half2_rn(st[2 * cp][j + e], st[2 * cp + 1][j + e]);
            v[e] = *reinterpret_cast<uint32_t*>(&h);
        }
        *(uint4*)&g_BP1[(size_t)(64 + cp) * MTOT + m0 + j] = *(uint4*)v;
    }
}

// ---------------------------------------------------------------------------
// Kernel 4 (launch #4 — PROFILED): GEMM1, fp16 mma, warp tile 64x64.
//   CTA tile 128x256, 8 warps (2x4), 4-stage cp.async (12KB/stage, 48KB).
//   Per warp per k-step: 32 LDS-wavefronts for 32 MMAs (was 24 for 16).
//   Per-output k-order identical to previous kernel -> bit-identical GEMM.
// ---------------------------------------------------------------------------
__global__ void __launch_bounds__(256) gemm1_kernel()
{
    __shared__ uint32_t sm[4 * 3072];   // stage: A 1024 u32 | B 2048 u32

    const int tid  = threadIdx.x;
    const int lane = tid & 31;
    const int wid  = tid >> 5;
    const int wm   = wid >> 2;          // 0..1  (64-row block)
    const int wn   = wid & 3;           // 0..3  (64-col block)
    const int g    = lane >> 2;
    const int t    = lane & 3;

    const int j0 = blockIdx.x * 256;
    const int i0 = blockIdx.y * 128;

    const int arow = tid >> 1;
    const int akh  = tid & 1;
    const int bkp  = tid >> 5;          // B k-pair row 0..7
    const int bcol = (tid & 31) * 8;    // B col group (8 u32)
    const int bsw  = bcol ^ (bkp << 3); // swizzled col base (8-aligned)

    const uint32_t a_dst0 = (uint32_t)__cvta_generic_to_shared(&sm[arow * 8 + akh * 4]);
    const uint32_t b_dst0 = (uint32_t)__cvta_generic_to_shared(&sm[1024 + bkp * 256 + bsw]);
    const __half*   a_src0 = g_W1h + (size_t)(i0 + arow) * C1 + akh * 8;
    const uint32_t* b_src0 = g_BP1 + (size_t)bkp * MTOT + j0 + bcol;

    float acc[4][8][4];
    #pragma unroll
    for (int mt = 0; mt < 4; mt++)
        #pragma unroll
        for (int nt = 0; nt < 8; nt++)
            #pragma unroll
            for (int e = 0; e < 4; e++) acc[mt][nt][e] = 0.0f;

    #define G1_ISSUE(step)                                                    \
    {                                                                         \
        int s_ = (step) & 3;                                                  \
        cp_async16(a_dst0 + s_ * 12288, a_src0 + (step) * 16);                \
        cp_async16(b_dst0 + s_ * 12288, b_src0 + (size_t)(step) * 8 * MTOT);  \
        cp_async16(b_dst0 + s_ * 12288 + 16,                                  \
                   b_src0 + (size_t)(step) * 8 * MTOT + 4);                   \
        CP_COMMIT();                                                          \
    }

    #define G1_COMPUTE(s)                                                     \
    {                                                                         \
        const uint32_t* As = sm + (s) * 3072;                                 \
        const uint32_t* Bs = sm + (s) * 3072 + 1024;                          \
        uint32_t bf[8][2];                                                    \
        _Pragma("unroll")                                                     \
        for (int nt = 0; nt < 8; nt++) {                                      \
            int n = wn * 64 + nt * 8 + g;                                     \
            bf[nt][0] = Bs[t * 256 + (n ^ (t << 3))];                         \
            bf[nt][1] = Bs[(t + 4) * 256 + (n ^ ((t + 4) << 3))];             \
        }                                                                     \
        _Pragma("unroll")                                                     \
        for (int mt = 0; mt < 4; mt++) {                                      \
            int r = wm * 64 + mt * 16 + g;                                    \
            uint32_t ah[4];                                                   \
            ah[0] = As[r * 8 + t];                                            \
            ah[1] = As[(r + 8) * 8 + t];                                      \
            ah[2] = As[r * 8 + t + 4];                                        \
            ah[3] = As[(r + 8) * 8 + t + 4];                                  \
            _Pragma("unroll")                                                 \
            for (int nt = 0; nt < 8; nt++)                                    \
                mma16816(acc[mt][nt], ah, bf[nt]);                            \
        }                                                                     \
    }

    G1_ISSUE(0); G1_ISSUE(1); G1_ISSUE(2);

    #pragma unroll 1
    for (int i = 0; i < 21; i++) {
        CP_WAIT(2);
        __syncthreads();
        G1_ISSUE(i + 3);
        G1_COMPUTE(i & 3);
        __syncthreads();
    }
    CP_WAIT(2); __syncthreads(); G1_COMPUTE(21 & 3);
    CP_WAIT(1); __syncthreads(); G1_COMPUTE(22 & 3);
    CP_WAIT(0); __syncthreads(); G1_COMPUTE(23 & 3);

    // ---- store C tile ----
    #pragma unroll
    for (int mt = 0; mt < 4; mt++) {
        #pragma unroll
        for (int nt = 0; nt < 8; nt++) {
            int row = i0 + wm * 64 + mt * 16 + g;
            int col = j0 + wn * 64 + nt * 8 + 2 * t;
            *(float2*)&g_h1[(size_t)row * MTOT + col] =
                make_float2(acc[mt][nt][0], acc[mt][nt][1]);
            *(float2*)&g_h1[(size_t)(row + 8) * MTOT + col] =
                make_float2(acc[mt][nt][2], acc[mt][nt][3]);
        }
    }

    // ---- BN1 partials: one (sum,sumsq) per channel per 256-col block ----
    __syncthreads();
    float* Ssum = (float*)sm;             // [16][128]
    float* Ssq  = (float*)(sm + 2048);    // [16][128]
    const int ci = wn * 4 + t;
    #pragma unroll
    for (int mt = 0; mt < 4; mt++) {
        int r0 = wm * 64 + mt * 16 + g;
        float s0 = 0.f, q0 = 0.f, s1 = 0.f, q1 = 0.f;
        #pragma unroll
        for (int nt = 0; nt < 8; nt++) {
            float e0 = acc[mt][nt][0], e1 = acc[mt][nt][1];
            float e2 = acc[mt][nt][2], e3 = acc[mt][nt][3];
            s0 += e0 + e1;  q0 += e0 * e0 + e1 * e1;
            s1 += e2 + e3;  q1 += e2 * e2 + e3 * e3;
        }
        Ssum[ci * 128 + r0]     = s0;  Ssq[ci * 128 + r0]     = q0;
        Ssum[ci * 128 + r0 + 8] = s1;  Ssq[ci * 128 + r0 + 8] = q1;
    }
    __syncthreads();
    if (tid < 128) {
        float s = 0.f;
        #pragma unroll
        for (int c = 0; c < 16; c++) s += Ssum[c * 128 + tid];
        g_psA[(size_t)(i0 + tid) * GRIDX + blockIdx.x] = s;   // 0..255 used; tail stays 0
    } else {
        int r = tid - 128;
        float q = 0.f;
        #pragma unroll
        for (int c = 0; c < 16; c++) q += Ssq[c * 128 + r];
        g_pqA[(size_t)(i0 + r) * GRIDX + blockIdx.x] = q;
    }
    #undef G1_ISSUE
    #undef G1_COMPUTE
}

// ---------------------------------------------------------------------------
// Kernel 5: GEMM2 — proven HMMA 2-stage path. H2 = W2 @ relu(BN1(H1)).
// ---------------------------------------------------------------------------
#define MMA_COMPUTE(ASBUF, BSBUF)                                             \
{                                                                             \
    uint32_t bf[4][2];                                                        \
    _Pragma("unroll")                                                         \
    for (int nt = 0; nt < 4; nt++) {                                          \
        int n = wn * 32 + nt * 8 + g;                                         \
        bf[nt][0] = (BSBUF)[t * 128 + (n ^ (t << 3))];                        \
        bf[nt][1] = (BSBUF)[(t + 4) * 128 + (n ^ ((t + 4) << 3))];            \
    }                                                                         \
    _Pragma("unroll")                                                         \
    for (int mt = 0; mt < 4; mt++) {                                          \
        int r = wm * 64 + mt * 16 + g;                                        \
        uint32_t ah[4];                                                       \
        ah[0] = (ASBUF)[r * 8 + t];                                           \
        ah[1] = (ASBUF)[(r + 8) * 8 + t];                                     \
        ah[2] = (ASBUF)[r * 8 + t + 4];                                       \
        ah[3] = (ASBUF)[(r + 8) * 8 + t + 4];                                 \
        _Pragma("unroll")                                                     \
        for (int nt = 0; nt < 4; nt++)                                        \
            mma16816(acc[mt][nt], ah, bf[nt]);                                \
    }                                                                         \
}

__global__ void __launch_bounds__(256, 2) gemm2_kernel()
{
    __shared__ uint32_t As[2][128 * 8];
    __shared__ uint32_t Bs[2][8 * 128];

    const int tid  = threadIdx.x;
    const int lane = tid & 31;
    const int wid  = tid >> 5;
    const int wm   = wid >> 2;
    const int wn   = wid & 3;
    const int g    = lane >> 2;
    const int t    = lane & 3;

    const int j0 = blockIdx.x * 128;
    const int i0 = blockIdx.y * 128;

    const int arow = tid >> 1;
    const int akh  = tid & 1;
    const int brp  = tid >> 5;
    const int bc0  = lane * 4;

    float acc[4][4][4];
    #pragma unroll
    for (int mt = 0; mt < 4; mt++)
        #pragma unroll
        for (int nt = 0; nt < 4; nt++)
            #pragma unroll
            for (int e = 0; e < 4; e++) acc[mt][nt][e] = 0.0f;

    uint4 ra;
    uint32_t pB[4];

    #define G2_LDG(kt)                                                        \
    {                                                                         \
        ra = *(const uint4*)(g_W2h + (size_t)(i0 + arow) * C2 + (kt) + akh * 8); \
        int k0 = (kt) + brp * 2;                                              \
        const float* s0 = g_h1 + (size_t)k0 * MTOT + j0 + bc0;                \
        float4 rb0 = *(const float4*)s0;                                      \
        float4 rb1 = *(const float4*)(s0 + MTOT);                             \
        float2 q0 = g_ss1[k0], q1 = g_ss1[k0 + 1];                            \
        const float* x0 = &rb0.x; const float* x1 = &rb1.x;                   \
        _Pragma("unroll")                                                     \
        for (int e = 0; e < 4; e++) {                                         \
            float u0 = fmaxf(fmaf(x0[e], q0.x, q0.y), 0.0f);                  \
            float u1 = fmaxf(fmaf(x1[e], q1.x, q1.y), 0.0f);                  \
            __half2 h = __floats2half2_rn(u0, u1);                            \
            pB[e] = *reinterpret_cast<uint32_t*>(&h);                         \
        }                                                                     \
    }

    #define G2_STS(buf)                                                       \
    {                                                                         \
        *(uint4*)&As[buf][arow * 8 + akh * 4] = ra;                           \
        int col = bc0 ^ (brp << 3);                                           \
        *(uint4*)&Bs[buf][brp * 128 + col] = *(uint4*)pB;                     \
    }

    G2_LDG(0);
    G2_STS(0);
    __syncthreads();

    int buf = 0;
    for (int kt = 16; kt < C2; kt += 16) {
        G2_LDG(kt);
        MMA_COMPUTE(As[buf], Bs[buf]);
        G2_STS(buf ^ 1);
        __syncthreads();
        buf ^= 1;
    }
    MMA_COMPUTE(As[buf], Bs[buf]);

    // store + BN partials
    #pragma unroll
    for (int mt = 0; mt < 4; mt++) {
        #pragma unroll
        for (int nt = 0; nt < 4; nt++) {
            int row = i0 + wm * 64 + mt * 16 + g;
            int col = j0 + wn * 32 + nt * 8 + 2 * t;
            *(float2*)&g_h2[(size_t)row * MTOT + col] =
                make_float2(acc[mt][nt][0], acc[mt][nt][1]);
            *(float2*)&g_h2[(size_t)(row + 8) * MTOT + col] =
                make_float2(acc[mt][nt][2], acc[mt][nt][3]);
        }
    }
    __syncthreads();
    float* Ssum = (float*)As;
    float* Ssq  = (float*)Bs;
    const int ci = wn * 4 + t;
    #pragma unroll
    for (int mt = 0; mt < 4; mt++) {
        int r0 = wm * 64 + mt * 16 + g;
        float s0 = 0.f, q0 = 0.f, s1 = 0.f, q1 = 0.f;
        #pragma unroll
        for (int nt = 0; nt < 4; nt++) {
            float e0 = acc[mt][nt][0], e1 = acc[mt][nt][1];
            float e2 = acc[mt][nt][2], e3 = acc[mt][nt][3];
            s0 += e0 + e1;  q0 += e0 * e0 + e1 * e1;
            s1 += e2 + e3;  q1 += e2 * e2 + e3 * e3;
        }
        Ssum[ci * 128 + r0]     = s0;  Ssq[ci * 128 + r0]     = q0;
        Ssum[ci * 128 + r0 + 8] = s1;  Ssq[ci * 128 + r0 + 8] = q1;
    }
    __syncthreads();
    if (tid < 128) {
        float s = 0.f;
        #pragma unroll
        for (int c = 0; c < 16; c++) s += Ssum[c * 128 + tid];
        g_psB[(size_t)(i0 + tid) * GRIDX + blockIdx.x] = s;
    } else {
        int r = tid - 128;
        float q = 0.f;
        #pragma unroll
        for (int c = 0; c < 16; c++) q += Ssq[c * 128 + r];
        g_pqB[(size_t)(i0 + r) * GRIDX + blockIdx.x] = q;
    }
    #undef G2_LDG
    #undef G2_STS
}

// ---------------------------------------------------------------------------
// Kernel 6: reduce per-block partials -> per-channel (scale, shift)
// ---------------------------------------------------------------------------
__global__ void __launch_bounds__(256) bn_reduce_kernel(
    const float* __restrict__ g, const float* __restrict__ beta, int which)
{
    const int c   = blockIdx.x;
    const int tid = threadIdx.x;
    const float* ps = (which == 1) ? g_psA : g_psB;
    const float* pq = (which == 1) ? g_pqA : g_pqB;

    double s = (double)ps[(size_t)c * GRIDX + tid] + (double)ps[(size_t)c * GRIDX + tid + 256];
    double q = (double)pq[(size_t)c * GRIDX + tid] + (double)pq[(size_t)c * GRIDX + tid + 256];

    __shared__ double r1[256], r2[256];
    r1[tid] = s;  r2[tid] = q;
    __syncthreads();
    for (int o = 128; o > 0; o >>= 1) {
        if (tid < o) { r1[tid] += r1[tid + o]; r2[tid] += r2[tid + o]; }
        __syncthreads();
    }
    if (tid == 0) {
        double mean = r1[0] / (double)MTOT;
        double var  = r2[0] / (double)MTOT - mean * mean;
        double rs   = 1.0 / sqrt(var + 1e-5);
        float scale = (float)((double)g[c] * rs);
        float shift = (float)((double)beta[c] - mean * (double)g[c] * rs);
        if (which == 1) g_ss1[c] = make_float2(scale, shift);
        else            g_ss2[c] = make_float2(scale, shift);
    }
}

// ---------------------------------------------------------------------------
// Kernel 7: final BN2 + ReLU + layout transform [c][b*N+n] -> [b][c][n]
// ---------------------------------------------------------------------------
__global__ void __launch_bounds__(256) bn_out_kernel(float* __restrict__ out)
{
    size_t f = (size_t)blockIdx.x * blockDim.x + threadIdx.x;
    size_t e = f * 4;
    int c = (int)(e / MTOT);
    int m = (int)(e % MTOT);
    int b = m / NPTS;
    int n = m % NPTS;

    float4 v = ((const float4*)g_h2)[f];
    float2 ss = g_ss2[c];
    v.x = fmaxf(fmaf(v.x, ss.x, ss.y), 0.0f);
    v.y = fmaxf(fmaf(v.y, ss.x, ss.y), 0.0f);
    v.z = fmaxf(fmaf(v.z, ss.x, ss.y), 0.0f);
    v.w = fmaxf(fmaf(v.w, ss.x, ss.y), 0.0f);
    *(float4*)(out + ((size_t)b * C3 + c) * NPTS + n) = v;
}

// ---------------------------------------------------------------------------
// Launcher — gemm1 stays the 4th launch (ncu captures launch #4)
// ---------------------------------------------------------------------------
extern "C" void kernel_launch(void* const* d_in, const int* in_sizes, int n_in,
                              void* d_out, int out_size)
{
    const float* pp    = (const float*)d_in[0];
    const float* spp   = (const float*)d_in[1];
    const float* skip  = (const float*)d_in[2];
    const float* sfeat = (const float*)d_in[3];
    const float* W1    = (const float*)d_in[4];
    // d_in[5] = b1 (cancels inside BN)
    const float* g1    = (const float*)d_in[6];
    const float* be1   = (const float*)d_in[7];
    const float* W2    = (const float*)d_in[8];
    // d_in[9] = b2 (cancels inside BN)
    const float* g2    = (const float*)d_in[10];
    const float* be2   = (const float*)d_in[11];
    float* out = (float*)d_out;

    // #1: all independent preprocessing fused
    prep_all_kernel<<<PREP_TOTAL, 256>>>(W1, W2, skip, sfeat);

    // #2: 3-NN (2 points/thread, 256 blocks — proven config)
    knn_kernel<<<B_ * (NPTS / 256), 128>>>(pp, spp);

    // #3: interpolation -> g_BP1 rows 64..191
    interp_kernel<<<MTOT / 32, 256>>>();

    // #4 (PROFILED): GEMM1 (+BN1 partials), warp tile 64x64, CTA 128x256
    {
        dim3 grid(G1GX, C2 / 128);
        gemm1_kernel<<<grid, 256>>>();
    }
    bn_reduce_kernel<<<C2, 256>>>(g1, be1, 1);

    // GEMM2 (+BN2 partials): H2 = W2 @ relu(BN1(H1))
    {
        dim3 grid(GRIDX, C3 / 128);
        gemm2_kernel<<<grid, 256>>>();
    }
    bn_reduce_kernel<<<C3, 256>>>(g2, be2, 2);

    bn_out_kernel<<<(C3 * MTOT / 4) / 256, 256>>>(out);
}

// round 14
// speedup vs baseline: 1.4397x; 1.0246x over previous
#include <cuda_runtime.h>
#include <cuda_fp16.h>
#include <float.h>
#include <math.h>
#include <stdint.h>

// Problem constants
#define B_    8
#define NPTS  8192
#define NS    2048
#define D1    128
#define D2    256
#define C1    384      // D1 + D2
#define C2    256
#define C3    128
#define MTOT  (B_ * NPTS)   // 65536
#define GRIDX (MTOT / 128)  // 512 column blocks per GEMM

// ---------------------------------------------------------------------------
// Scratch (static device globals — no allocations allowed)
// ---------------------------------------------------------------------------
__device__ __align__(16) uint32_t g_BP1[(size_t)(C1 / 2) * MTOT]; // 48 MB GEMM1 B (packed fp16 k-pairs)
__device__ __align__(16) uint32_t g_BP2[(size_t)(C2 / 2) * MTOT]; // 32 MB h1 packed fp16 k-pairs (raw -> BN-applied in place)
__device__ float  g_h2[(size_t)C3 * MTOT];       // 32 MB GEMM2 out (pre-BN) [c][m]
__device__ float  g_sfT[(size_t)B_ * NS * D2];   // 16 MB sfeat transposed [b][s][c]
__device__ float4 g_w[MTOT];                     // per-point 3-NN weights
__device__ int4   g_i[MTOT];                     // per-point 3-NN indices
__device__ float2 g_ss1[C2];                     // BN1 (scale, shift)
__device__ float2 g_ss2[C3];                     // BN2 (scale, shift)
__device__ __align__(16) __half g_W1h[C2 * C1];  // fp16 weights, row-major
__device__ __align__(16) __half g_W2h[C3 * C2];
// per-block BN partials (deterministic reduction, no atomics)
__device__ float g_psA[C2 * GRIDX], g_pqA[C2 * GRIDX];
__device__ float g_psB[C3 * GRIDX], g_pqB[C3 * GRIDX];

__device__ __forceinline__ void mma16816(float* d, const uint32_t* a, const uint32_t* b) {
    asm volatile(
        "mma.sync.aligned.m16n8k16.row.col.f32.f16.f16.f32 "
        "{%0,%1,%2,%3}, {%4,%5,%6,%7}, {%8,%9}, {%0,%1,%2,%3};\n"
        : "+f"(d[0]), "+f"(d[1]), "+f"(d[2]), "+f"(d[3])
        : "r"(a[0]), "r"(a[1]), "r"(a[2]), "r"(a[3]), "r"(b[0]), "r"(b[1]));
}

__device__ __forceinline__ void cp_async16(uint32_t smem_addr, const void* gptr) {
    asm volatile("cp.async.ca.shared.global [%0], [%1], 16;\n"
                 :: "r"(smem_addr), "l"(gptr));
}
#define CP_COMMIT()  asm volatile("cp.async.commit_group;\n")
#define CP_WAIT(N)   asm volatile("cp.async.wait_group %0;\n" :: "n"(N))

// ---------------------------------------------------------------------------
// Kernel 1 (launch #1): fused prep — weights->fp16, skip pack, sfeat transpose
// ---------------------------------------------------------------------------
#define PREP_W_BLOCKS   384
#define PREP_PS_BLOCKS  4096
#define PREP_TR_BLOCKS  4096
#define PREP_TOTAL      (PREP_W_BLOCKS + PREP_PS_BLOCKS + PREP_TR_BLOCKS)

__global__ void __launch_bounds__(256) prep_all_kernel(
    const float* __restrict__ W1, const float* __restrict__ W2,
    const float* __restrict__ skip, const float* __restrict__ sfeat)
{
    const int bid = blockIdx.x;
    const int tid = threadIdx.x;

    if (bid < PREP_W_BLOCKS) {
        int i = bid * 256 + tid;
        if (i < C2 * C1) g_W1h[i] = __float2half_rn(W1[i]);
        if (i < C3 * C2) g_W2h[i] = __float2half_rn(W2[i]);
        return;
    }
    if (bid < PREP_W_BLOCKS + PREP_PS_BLOCKS) {
        int pb = bid - PREP_W_BLOCKS;
        int cp = pb >> 6;
        int m0 = ((pb & 63) * 256 + tid) * 4;
        int b  = m0 / NPTS;
        int n  = m0 % NPTS;
        const float* r0 = skip + ((size_t)b * D1 + 2 * cp)     * NPTS + n;
        const float* r1 = skip + ((size_t)b * D1 + 2 * cp + 1) * NPTS + n;
        float4 v0 = *(const float4*)r0;
        float4 v1 = *(const float4*)r1;
        uint32_t p[4];
        const float* x0 = &v0.x; const float* x1 = &v1.x;
        #pragma unroll
        for (int e = 0; e < 4; e++) {
            __half2 h = __floats2half2_rn(x0[e], x1[e]);
            p[e] = *reinterpret_cast<uint32_t*>(&h);
        }
        *(uint4*)&g_BP1[(size_t)cp * MTOT + m0] = *(uint4*)p;
        return;
    }
    {
        __shared__ float tile[32][33];
        int tb = bid - PREP_W_BLOCKS - PREP_PS_BLOCKS;
        int s0 = (tb & 63) * 32;
        int c0 = ((tb >> 6) & 7) * 32;
        int b  = tb >> 9;
        int tx = tid & 31;
        int ty = tid >> 5;

        #pragma unroll
        for (int r = 0; r < 32; r += 8)
            tile[ty + r][tx] = sfeat[((size_t)b * D2 + c0 + ty + r) * NS + s0 + tx];
        __syncthreads();
        #pragma unroll
        for (int r = 0; r < 32; r += 8)
            g_sfT[((size_t)b * NS + s0 + ty + r) * D2 + c0 + tx] = tile[tx][ty + r];
    }
}

// ---------------------------------------------------------------------------
// Kernel 2 (launch #2): 3-NN search — proven config: 2 pts/thread, 256 blocks
// ---------------------------------------------------------------------------
__global__ void __launch_bounds__(128) knn_kernel(
    const float* __restrict__ pp, const float* __restrict__ spp)
{
    __shared__ float4 ssmp[NS];

    const int b   = blockIdx.x >> 5;
    const int n0  = (blockIdx.x & 31) << 8;
    const int tid = threadIdx.x;

    const float* sb = spp + (size_t)b * 3 * NS;
    for (int s = tid; s < NS; s += 128) {
        float x = sb[s], y = sb[s + NS], z = sb[s + 2 * NS];
        ssmp[s] = make_float4(x, y, z, fmaf(x, x, fmaf(y, y, z * z)));
    }
    __syncthreads();

    const int nA = n0 + tid, nB = nA + 128;
    const float* pb = pp + (size_t)b * 3 * NPTS;
    const float ax = pb[nA], ay = pb[nA + NPTS], az = pb[nA + 2 * NPTS];
    const float bx = pb[nB], by = pb[nB + NPTS], bz = pb[nB + 2 * NPTS];

    float ad0 = FLT_MAX, ad1 = FLT_MAX, ad2 = FLT_MAX;
    float bd0 = FLT_MAX, bd1 = FLT_MAX, bd2 = FLT_MAX;
    int   ai0 = 0, ai1 = 0, ai2 = 0, bi0 = 0, bi1 = 0, bi2 = 0;

    #pragma unroll 4
    for (int j = 0; j < NS; j++) {
        float4 q  = ssmp[j];
        float sA = fmaf(-2.0f, fmaf(ax, q.x, fmaf(ay, q.y, az * q.z)), q.w);
        float sB = fmaf(-2.0f, fmaf(bx, q.x, fmaf(by, q.y, bz * q.z)), q.w);
        if (sA < ad2) {
            if (sA < ad1) {
                ad2 = ad1; ai2 = ai1;
                if (sA < ad0) { ad1 = ad0; ai1 = ai0; ad0 = sA; ai0 = j; }
                else          { ad1 = sA; ai1 = j; }
            } else { ad2 = sA; ai2 = j; }
        }
        if (sB < bd2) {
            if (sB < bd1) {
                bd2 = bd1; bi2 = bi1;
                if (sB < bd0) { bd1 = bd0; bi1 = bi0; bd0 = sB; bi0 = j; }
                else          { bd1 = sB; bi1 = j; }
            } else { bd2 = sB; bi2 = j; }
        }
    }

    {
        const float p2 = fmaf(ax, ax, fmaf(ay, ay, az * az));
        float a0 = 1.0f / ((ad0 + p2) + 1e-8f);
        float a1 = 1.0f / ((ad1 + p2) + 1e-8f);
        float a2 = 1.0f / ((ad2 + p2) + 1e-8f);
        float inv = 1.0f / (a0 + a1 + a2);
        g_w[b * NPTS + nA] = make_float4(a0 * inv, a1 * inv, a2 * inv, 0.0f);
        g_i[b * NPTS + nA] = make_int4(ai0, ai1, ai2, 0);
    }
    {
        const float p2 = fmaf(bx, bx, fmaf(by, by, bz * bz));
        float a0 = 1.0f / ((bd0 + p2) + 1e-8f);
        float a1 = 1.0f / ((bd1 + p2) + 1e-8f);
        float a2 = 1.0f / ((bd2 + p2) + 1e-8f);
        float inv = 1.0f / (a0 + a1 + a2);
        g_w[b * NPTS + nB] = make_float4(a0 * inv, a1 * inv, a2 * inv, 0.0f);
        g_i[b * NPTS + nB] = make_int4(bi0, bi1, bi2, 0);
    }
}

// ---------------------------------------------------------------------------
// Kernel 3 (launch #3): interpolation -> g_BP1 rows 64..191 (half2 packed)
// ---------------------------------------------------------------------------
__global__ void __launch_bounds__(256) interp_kernel()
{
    __shared__ float  st[D2][33];
    __shared__ float4 sw[32];
    __shared__ int4   si[32];

    const int m0  = blockIdx.x * 32;
    const int b   = m0 / NPTS;
    const int tid = threadIdx.x;

    if (tid < 32) { sw[tid] = g_w[m0 + tid]; si[tid] = g_i[m0 + tid]; }
    __syncthreads();

    const float* fT = g_sfT + (size_t)b * NS * D2;
    #pragma unroll 8
    for (int p = 0; p < 32; p++) {
        float4 w = sw[p];
        int4   ii = si[p];
        float v = fmaf(w.x, __ldg(fT + (size_t)ii.x * D2 + tid),
                  fmaf(w.y, __ldg(fT + (size_t)ii.y * D2 + tid),
                       w.z * __ldg(fT + (size_t)ii.z * D2 + tid)));
        st[tid][p] = v;
    }
    __syncthreads();

    const int cpb = tid >> 3;
    const int j   = (tid & 7) << 2;
    #pragma unroll
    for (int r = 0; r < 4; r++) {
        int cp = r * 32 + cpb;
        uint32_t v[4];
        #pragma unroll
        for (int e = 0; e < 4; e++) {
            __half2 h = __floats2half2_rn(st[2 * cp][j + e], st[2 * cp + 1][j + e]);
            v[e] = *reinterpret_cast<uint32_t*>(&h);
        }
        *(uint4*)&g_BP1[(size_t)(64 + cp) * MTOT + m0 + j] = *(uint4*)v;
    }
}

// ---------------------------------------------------------------------------
// Shared MMA compute (As [m][kpair], Bs [kpair][n ^ (kp<<3)])
// ---------------------------------------------------------------------------
#define MMA_COMPUTE(ASBUF, BSBUF)                                             \
{                                                                             \
    uint32_t bf[4][2];                                                        \
    _Pragma("unroll")                                                         \
    for (int nt = 0; nt < 4; nt++) {                                          \
        int n = wn * 32 + nt * 8 + g;                                         \
        bf[nt][0] = (BSBUF)[t * 128 + (n ^ (t << 3))];                        \
        bf[nt][1] = (BSBUF)[(t + 4) * 128 + (n ^ ((t + 4) << 3))];            \
    }                                                                         \
    _Pragma("unroll")                                                         \
    for (int mt = 0; mt < 4; mt++) {                                          \
        int r = wm * 64 + mt * 16 + g;                                        \
        uint32_t ah[4];                                                       \
        ah[0] = (ASBUF)[r * 8 + t];                                           \
        ah[1] = (ASBUF)[(r + 8) * 8 + t];                                     \
        ah[2] = (ASBUF)[r * 8 + t + 4];                                       \
        ah[3] = (ASBUF)[(r + 8) * 8 + t + 4];                                 \
        _Pragma("unroll")                                                     \
        for (int nt = 0; nt < 4; nt++)                                        \
            mma16816(acc[mt][nt], ah, bf[nt]);                                \
    }                                                                         \
}

// BN partial-stat emission (sum/sumsq from fp32 accumulators)
#define BN_PARTIALS(PSUM, PSQ, SS_SMEM, SQ_SMEM)                              \
{                                                                             \
    __syncthreads();                                                          \
    float* Ssum = (SS_SMEM);                                                  \
    float* Ssq  = (SQ_SMEM);                                                  \
    const int ci = wn * 4 + t;                                                \
    _Pragma("unroll")                                                         \
    for (int mt = 0; mt < 4; mt++) {                                          \
        int r0 = wm * 64 + mt * 16 + g;                                       \
        float s0 = 0.f, q0 = 0.f, s1 = 0.f, q1 = 0.f;                         \
        _Pragma("unroll")                                                     \
        for (int nt = 0; nt < 4; nt++) {                                      \
            float e0 = acc[mt][nt][0], e1 = acc[mt][nt][1];                   \
            float e2 = acc[mt][nt][2], e3 = acc[mt][nt][3];                   \
            s0 += e0 + e1;  q0 += e0 * e0 + e1 * e1;                          \
            s1 += e2 + e3;  q1 += e2 * e2 + e3 * e3;                          \
        }                                                                     \
        Ssum[ci * 128 + r0]     = s0;  Ssq[ci * 128 + r0]     = q0;           \
        Ssum[ci * 128 + r0 + 8] = s1;  Ssq[ci * 128 + r0 + 8] = q1;           \
    }                                                                         \
    __syncthreads();                                                          \
    if (tid < 128) {                                                          \
        float s = 0.f;                                                        \
        _Pragma("unroll")                                                     \
        for (int c = 0; c < 16; c++) s += Ssum[c * 128 + tid];                \
        (PSUM)[(size_t)(i0 + tid) * GRIDX + blockIdx.x] = s;                  \
    } else {                                                                  \
        int r = tid - 128;                                                    \
        float q = 0.f;                                                        \
        _Pragma("unroll")                                                     \
        for (int c = 0; c < 16; c++) q += Ssq[c * 128 + r];                   \
        (PSQ)[(size_t)(i0 + r) * GRIDX + blockIdx.x] = q;                     \
    }                                                                         \
}

// ---------------------------------------------------------------------------
// Kernel 4 (launch #4 — PROFILED): GEMM1, fp16 mma, 4-stage cp.async,
//   128x128 CTA / 64x32 warp tile (the measured-70.6us config).
//   NEW epilogue: writes h1 directly as packed raw fp16 k-pairs to g_BP2
//   (channel c paired with c+1 via lane shuffle) + BN1 partials from fp32 acc.
// ---------------------------------------------------------------------------
__global__ void __launch_bounds__(256) gemm1_kernel()
{
    __shared__ uint32_t As[4][128 * 8];
    __shared__ uint32_t Bs[4][8 * 128];

    const int tid  = threadIdx.x;
    const int lane = tid & 31;
    const int wid  = tid >> 5;
    const int wm   = wid >> 2;
    const int wn   = wid & 3;
    const int g    = lane >> 2;
    const int t    = lane & 3;

    const int j0 = blockIdx.x * 128;
    const int i0 = blockIdx.y * 128;

    const int arow = tid >> 1;
    const int akh  = tid & 1;
    const int brp  = tid >> 5;
    const int bc0  = lane * 4;

    const uint32_t a_dst0 = (uint32_t)__cvta_generic_to_shared(&As[0][arow * 8 + akh * 4]);
    const uint32_t b_dst0 = (uint32_t)__cvta_generic_to_shared(&Bs[0][brp * 128 + (bc0 ^ (brp << 3))]);
    const __half*   a_src0 = g_W1h + (size_t)(i0 + arow) * C1 + akh * 8;
    const uint32_t* b_src0 = g_BP1 + (size_t)brp * MTOT + j0 + bc0;

    float acc[4][4][4];
    #pragma unroll
    for (int mt = 0; mt < 4; mt++)
        #pragma unroll
        for (int nt = 0; nt < 4; nt++)
            #pragma unroll
            for (int e = 0; e < 4; e++) acc[mt][nt][e] = 0.0f;

    #define G1_ISSUE(step)                                                    \
    {                                                                         \
        int s_ = (step) & 3;                                                  \
        cp_async16(a_dst0 + s_ * 4096, a_src0 + (step) * 16);                 \
        cp_async16(b_dst0 + s_ * 4096, b_src0 + (size_t)(step) * 8 * MTOT);   \
        CP_COMMIT();                                                          \
    }

    G1_ISSUE(0); G1_ISSUE(1); G1_ISSUE(2);

    #pragma unroll 1
    for (int i = 0; i < 21; i++) {
        CP_WAIT(2);
        __syncthreads();
        G1_ISSUE(i + 3);
        MMA_COMPUTE(As[i & 3], Bs[i & 3]);
    }
    CP_WAIT(2); __syncthreads(); MMA_COMPUTE(As[21 & 3], Bs[21 & 3]);
    CP_WAIT(1); __syncthreads(); MMA_COMPUTE(As[22 & 3], Bs[22 & 3]);
    CP_WAIT(0); __syncthreads(); MMA_COMPUTE(As[23 & 3], Bs[23 & 3]);

    // ---- epilogue: pack h1 -> raw fp16 k-pairs in g_BP2 ----
    // Lane L holds rows (r, r+8), cols (c, c+1) with r = wm*64+mt*16+g.
    // Channel pair (r, r+1): partner row r+1 lives in lane L+4 (g+1).
    #pragma unroll
    for (int mt = 0; mt < 4; mt++) {
        #pragma unroll
        for (int nt = 0; nt < 4; nt++) {
            float v0 = acc[mt][nt][0], v1 = acc[mt][nt][1];
            float v2 = acc[mt][nt][2], v3 = acc[mt][nt][3];
            float p0 = __shfl_down_sync(0xFFFFFFFFu, v0, 4);
            float p1 = __shfl_down_sync(0xFFFFFFFFu, v1, 4);
            float p2 = __shfl_down_sync(0xFFFFFFFFu, v2, 4);
            float p3 = __shfl_down_sync(0xFFFFFFFFu, v3, 4);
            if (!(g & 1)) {
                int r   = wm * 64 + mt * 16 + g;        // even row
                int cp0 = (i0 + r) >> 1;
                int col = j0 + wn * 32 + nt * 8 + 2 * t;
                __half2 h0 = __floats2half2_rn(v0, p0); // (ch r, ch r+1) @ col
                __half2 h1 = __floats2half2_rn(v1, p1); // @ col+1
                uint2 w0 = make_uint2(*(uint32_t*)&h0, *(uint32_t*)&h1);
                *(uint2*)&g_BP2[(size_t)cp0 * MTOT + col] = w0;
                __half2 h2 = __floats2half2_rn(v2, p2); // (ch r+8, r+9)
                __half2 h3 = __floats2half2_rn(v3, p3);
                uint2 w1 = make_uint2(*(uint32_t*)&h2, *(uint32_t*)&h3);
                *(uint2*)&g_BP2[(size_t)(cp0 + 4) * MTOT + col] = w1;
            }
        }
    }

    BN_PARTIALS(g_psA, g_pqA, (float*)As, (float*)Bs);
    #undef G1_ISSUE
}

// ---------------------------------------------------------------------------
// Kernel 5: bn1_apply — in-place BN1 + ReLU on packed fp16 pairs in g_BP2.
// ---------------------------------------------------------------------------
__global__ void __launch_bounds__(256) bn1_apply_kernel()
{
    int idx = blockIdx.x * 256 + threadIdx.x;      // over 128 * (MTOT/4)
    int cp  = idx >> 14;                           // MTOT/4 = 16384
    int m0  = (idx & 16383) * 4;
    float2 s0 = g_ss1[2 * cp];
    float2 s1 = g_ss1[2 * cp + 1];
    uint4 v = *(uint4*)&g_BP2[(size_t)cp * MTOT + m0];
    uint32_t* pv = (uint32_t*)&v;
    #pragma unroll
    for (int e = 0; e < 4; e++) {
        __half2 h = *reinterpret_cast<__half2*>(&pv[e]);
        float lo = __low2float(h), hi = __high2float(h);
        lo = fmaxf(fmaf(lo, s0.x, s0.y), 0.0f);
        hi = fmaxf(fmaf(hi, s1.x, s1.y), 0.0f);
        __half2 o = __floats2half2_rn(lo, hi);
        pv[e] = *reinterpret_cast<uint32_t*>(&o);
    }
    *(uint4*)&g_BP2[(size_t)cp * MTOT + m0] = v;
}

// ---------------------------------------------------------------------------
// Kernel 6: GEMM2 — pure-copy clone of gemm1 (K=256, 16 k-steps).
//   H2 = W2 @ relu(BN1(H1)); B already transformed+packed in g_BP2.
// ---------------------------------------------------------------------------
__global__ void __launch_bounds__(256) gemm2_kernel()
{
    __shared__ uint32_t As[4][128 * 8];
    __shared__ uint32_t Bs[4][8 * 128];

    const int tid  = threadIdx.x;
    const int lane = tid & 31;
    const int wid  = tid >> 5;
    const int wm   = wid >> 2;
    const int wn   = wid & 3;
    const int g    = lane >> 2;
    const int t    = lane & 3;

    const int j0 = blockIdx.x * 128;
    const int i0 = 0;

    const int arow = tid >> 1;
    const int akh  = tid & 1;
    const int brp  = tid >> 5;
    const int bc0  = lane * 4;

    const uint32_t a_dst0 = (uint32_t)__cvta_generic_to_shared(&As[0][arow * 8 + akh * 4]);
    const uint32_t b_dst0 = (uint32_t)__cvta_generic_to_shared(&Bs[0][brp * 128 + (bc0 ^ (brp << 3))]);
    const __half*   a_src0 = g_W2h + (size_t)arow * C2 + akh * 8;
    const uint32_t* b_src0 = g_BP2 + (size_t)brp * MTOT + j0 + bc0;

    float acc[4][4][4];
    #pragma unroll
    for (int mt = 0; mt < 4; mt++)
        #pragma unroll
        for (int nt = 0; nt < 4; nt++)
            #pragma unroll
            for (int e = 0; e < 4; e++) acc[mt][nt][e] = 0.0f;

    #define G2_ISSUE(step)                                                    \
    {                                                                         \
        int s_ = (step) & 3;                                                  \
        cp_async16(a_dst0 + s_ * 4096, a_src0 + (step) * 16);                 \
        cp_async16(b_dst0 + s_ * 4096, b_src0 + (size_t)(step) * 8 * MTOT);   \
        CP_COMMIT();                                                          \
    }

    G2_ISSUE(0); G2_ISSUE(1); G2_ISSUE(2);

    #pragma unroll 1
    for (int i = 0; i < 13; i++) {
        CP_WAIT(2);
        __syncthreads();
        G2_ISSUE(i + 3);
        MMA_COMPUTE(As[i & 3], Bs[i & 3]);
    }
    CP_WAIT(2); __syncthreads(); MMA_COMPUTE(As[13 & 3], Bs[13 & 3]);
    CP_WAIT(1); __syncthreads(); MMA_COMPUTE(As[14 & 3], Bs[14 & 3]);
    CP_WAIT(0); __syncthreads(); MMA_COMPUTE(As[15 & 3], Bs[15 & 3]);

    // store h2 fp32 + BN2 partials
    #pragma unroll
    for (int mt = 0; mt < 4; mt++) {
        #pragma unroll
        for (int nt = 0; nt < 4; nt++) {
            int row = wm * 64 + mt * 16 + g;
            int col = j0 + wn * 32 + nt * 8 + 2 * t;
            *(float2*)&g_h2[(size_t)row * MTOT + col] =
                make_float2(acc[mt][nt][0], acc[mt][nt][1]);
            *(float2*)&g_h2[(size_t)(row + 8) * MTOT + col] =
                make_float2(acc[mt][nt][2], acc[mt][nt][3]);
        }
    }

    BN_PARTIALS(g_psB, g_pqB, (float*)As, (float*)Bs);
    #undef G2_ISSUE
}

// ---------------------------------------------------------------------------
// Kernel 7: reduce per-block partials -> per-channel (scale, shift)
// ---------------------------------------------------------------------------
__global__ void __launch_bounds__(256) bn_reduce_kernel(
    const float* __restrict__ g, const float* __restrict__ beta, int which)
{
    const int c   = blockIdx.x;
    const int tid = threadIdx.x;
    const float* ps = (which == 1) ? g_psA : g_psB;
    const float* pq = (which == 1) ? g_pqA : g_pqB;

    double s = (double)ps[(size_t)c * GRIDX + tid] + (double)ps[(size_t)c * GRIDX + tid + 256];
    double q = (double)pq[(size_t)c * GRIDX + tid] + (double)pq[(size_t)c * GRIDX + tid + 256];

    __shared__ double r1[256], r2[256];
    r1[tid] = s;  r2[tid] = q;
    __syncthreads();
    for (int o = 128; o > 0; o >>= 1) {
        if (tid < o) { r1[tid] += r1[tid + o]; r2[tid] += r2[tid + o]; }
        __syncthreads();
    }
    if (tid == 0) {
        double mean = r1[0] / (double)MTOT;
        double var  = r2[0] / (double)MTOT - mean * mean;
        double rs   = 1.0 / sqrt(var + 1e-5);
        float scale = (float)((double)g[c] * rs);
        float shift = (float)((double)beta[c] - mean * (double)g[c] * rs);
        if (which == 1) g_ss1[c] = make_float2(scale, shift);
        else            g_ss2[c] = make_float2(scale, shift);
    }
}

// ---------------------------------------------------------------------------
// Kernel 8: final BN2 + ReLU + layout transform [c][b*N+n] -> [b][c][n]
// ---------------------------------------------------------------------------
__global__ void __launch_bounds__(256) bn_out_kernel(float* __restrict__ out)
{
    size_t f = (size_t)blockIdx.x * blockDim.x + threadIdx.x;
    size_t e = f * 4;
    int c = (int)(e / MTOT);
    int m = (int)(e % MTOT);
    int b = m / NPTS;
    int n = m % NPTS;

    float4 v = ((const float4*)g_h2)[f];
    float2 ss = g_ss2[c];
    v.x = fmaxf(fmaf(v.x, ss.x, ss.y), 0.0f);
    v.y = fmaxf(fmaf(v.y, ss.x, ss.y), 0.0f);
    v.z = fmaxf(fmaf(v.z, ss.x, ss.y), 0.0f);
    v.w = fmaxf(fmaf(v.w, ss.x, ss.y), 0.0f);
    *(float4*)(out + ((size_t)b * C3 + c) * NPTS + n) = v;
}

// ---------------------------------------------------------------------------
// Launcher — gemm1 stays the 4th launch (ncu captures launch #4)
// ---------------------------------------------------------------------------
extern "C" void kernel_launch(void* const* d_in, const int* in_sizes, int n_in,
                              void* d_out, int out_size)
{
    const float* pp    = (const float*)d_in[0];
    const float* spp   = (const float*)d_in[1];
    const float* skip  = (const float*)d_in[2];
    const float* sfeat = (const float*)d_in[3];
    const float* W1    = (const float*)d_in[4];
    // d_in[5] = b1 (cancels inside BN)
    const float* g1    = (const float*)d_in[6];
    const float* be1   = (const float*)d_in[7];
    const float* W2    = (const float*)d_in[8];
    // d_in[9] = b2 (cancels inside BN)
    const float* g2    = (const float*)d_in[10];
    const float* be2   = (const float*)d_in[11];
    float* out = (float*)d_out;

    // #1: fused preprocessing
    prep_all_kernel<<<PREP_TOTAL, 256>>>(W1, W2, skip, sfeat);

    // #2: 3-NN
    knn_kernel<<<B_ * (NPTS / 256), 128>>>(pp, spp);

    // #3: interpolation -> g_BP1 rows 64..191
    interp_kernel<<<MTOT / 32, 256>>>();

    // #4 (PROFILED): GEMM1 -> packed raw fp16 h1 + BN1 partials
    {
        dim3 grid(GRIDX, C2 / 128);
        gemm1_kernel<<<grid, 256>>>();
    }
    bn_reduce_kernel<<<C2, 256>>>(g1, be1, 1);

    // #6: BN1 apply + ReLU, in place on packed h1
    bn1_apply_kernel<<<(C2 / 2) * (MTOT / 4) / 256, 256>>>();

    // #7: GEMM2 (pure copy loaders) -> h2 + BN2 partials
    gemm2_kernel<<<GRIDX, 256>>>();
    bn_reduce_kernel<<<C3, 256>>>(g2, be2, 2);

    // #9: BN2 apply + ReLU + transpose to [B,128,N]
    bn_out_kernel<<<(C3 * MTOT / 4) / 256, 256>>>(out);
}

// round 15
// speedup vs baseline: 1.4773x; 1.0261x over previous
#include <cuda_runtime.h>
#include <cuda_fp16.h>
#include <float.h>
#include <math.h>
#include <stdint.h>

// Problem constants
#define B_    8
#define NPTS  8192
#define NS    2048
#define D1    128
#define D2    256
#define C1    384      // D1 + D2
#define C2    256
#define C3    128
#define MTOT  (B_ * NPTS)   // 65536
#define GRIDX (MTOT / 128)  // 512 column blocks per GEMM

// ---------------------------------------------------------------------------
// Scratch (static device globals — no allocations allowed)
// ---------------------------------------------------------------------------
__device__ __align__(16) uint32_t g_BP1[(size_t)(C1 / 2) * MTOT]; // 48 MB GEMM1 B (packed fp16 k-pairs)
__device__ __align__(16) uint32_t g_BP2[(size_t)(C2 / 2) * MTOT]; // 32 MB h1 RAW packed fp16 k-pairs
__device__ float  g_h2[(size_t)C3 * MTOT];       // 32 MB GEMM2 out (pre-BN) [c][m]
__device__ float  g_sfT[(size_t)B_ * NS * D2];   // 16 MB sfeat transposed [b][s][c]
__device__ float4 g_w[MTOT];                     // per-point 3-NN weights
__device__ int4   g_i[MTOT];                     // per-point 3-NN indices
__device__ float2 g_ss1[C2];                     // BN1 (scale, shift) fp32
__device__ float2 g_ss2[C3];                     // BN2 (scale, shift)
__device__ __align__(4) __half g_sc1h[C2];       // BN1 scale, fp16 (for fragment fuse)
__device__ __align__(4) __half g_sh1h[C2];       // BN1 shift, fp16
__device__ __align__(16) __half g_W1h[C2 * C1];  // fp16 weights, row-major
__device__ __align__(16) __half g_W2h[C3 * C2];
// per-block BN partials (deterministic reduction, no atomics)
__device__ float g_psA[C2 * GRIDX], g_pqA[C2 * GRIDX];
__device__ float g_psB[C3 * GRIDX], g_pqB[C3 * GRIDX];

__device__ __forceinline__ void mma16816(float* d, const uint32_t* a, const uint32_t* b) {
    asm volatile(
        "mma.sync.aligned.m16n8k16.row.col.f32.f16.f16.f32 "
        "{%0,%1,%2,%3}, {%4,%5,%6,%7}, {%8,%9}, {%0,%1,%2,%3};\n"
        : "+f"(d[0]), "+f"(d[1]), "+f"(d[2]), "+f"(d[3])
        : "r"(a[0]), "r"(a[1]), "r"(a[2]), "r"(a[3]), "r"(b[0]), "r"(b[1]));
}

__device__ __forceinline__ void cp_async16(uint32_t smem_addr, const void* gptr) {
    asm volatile("cp.async.ca.shared.global [%0], [%1], 16;\n"
                 :: "r"(smem_addr), "l"(gptr));
}
#define CP_COMMIT()  asm volatile("cp.async.commit_group;\n")
#define CP_WAIT(N)   asm volatile("cp.async.wait_group %0;\n" :: "n"(N))

// ---------------------------------------------------------------------------
// Kernel 1 (launch #1): fused prep — weights->fp16, skip pack, sfeat transpose
// ---------------------------------------------------------------------------
#define PREP_W_BLOCKS   384
#define PREP_PS_BLOCKS  4096
#define PREP_TR_BLOCKS  4096
#define PREP_TOTAL      (PREP_W_BLOCKS + PREP_PS_BLOCKS + PREP_TR_BLOCKS)

__global__ void __launch_bounds__(256) prep_all_kernel(
    const float* __restrict__ W1, const float* __restrict__ W2,
    const float* __restrict__ skip, const float* __restrict__ sfeat)
{
    const int bid = blockIdx.x;
    const int tid = threadIdx.x;

    if (bid < PREP_W_BLOCKS) {
        int i = bid * 256 + tid;
        if (i < C2 * C1) g_W1h[i] = __float2half_rn(W1[i]);
        if (i < C3 * C2) g_W2h[i] = __float2half_rn(W2[i]);
        return;
    }
    if (bid < PREP_W_BLOCKS + PREP_PS_BLOCKS) {
        int pb = bid - PREP_W_BLOCKS;
        int cp = pb >> 6;
        int m0 = ((pb & 63) * 256 + tid) * 4;
        int b  = m0 / NPTS;
        int n  = m0 % NPTS;
        const float* r0 = skip + ((size_t)b * D1 + 2 * cp)     * NPTS + n;
        const float* r1 = skip + ((size_t)b * D1 + 2 * cp + 1) * NPTS + n;
        float4 v0 = *(const float4*)r0;
        float4 v1 = *(const float4*)r1;
        uint32_t p[4];
        const float* x0 = &v0.x; const float* x1 = &v1.x;
        #pragma unroll
        for (int e = 0; e < 4; e++) {
            __half2 h = __floats2half2_rn(x0[e], x1[e]);
            p[e] = *reinterpret_cast<uint32_t*>(&h);
        }
        *(uint4*)&g_BP1[(size_t)cp * MTOT + m0] = *(uint4*)p;
        return;
    }
    {
        __shared__ float tile[32][33];
        int tb = bid - PREP_W_BLOCKS - PREP_PS_BLOCKS;
        int s0 = (tb & 63) * 32;
        int c0 = ((tb >> 6) & 7) * 32;
        int b  = tb >> 9;
        int tx = tid & 31;
        int ty = tid >> 5;

        #pragma unroll
        for (int r = 0; r < 32; r += 8)
            tile[ty + r][tx] = sfeat[((size_t)b * D2 + c0 + ty + r) * NS + s0 + tx];
        __syncthreads();
        #pragma unroll
        for (int r = 0; r < 32; r += 8)
            g_sfT[((size_t)b * NS + s0 + ty + r) * D2 + c0 + tx] = tile[tx][ty + r];
    }
}

// ---------------------------------------------------------------------------
// Kernel 2 (launch #2): 3-NN search — proven config: 2 pts/thread, 256 blocks
// ---------------------------------------------------------------------------
__global__ void __launch_bounds__(128) knn_kernel(
    const float* __restrict__ pp, const float* __restrict__ spp)
{
    __shared__ float4 ssmp[NS];

    const int b   = blockIdx.x >> 5;
    const int n0  = (blockIdx.x & 31) << 8;
    const int tid = threadIdx.x;

    const float* sb = spp + (size_t)b * 3 * NS;
    for (int s = tid; s < NS; s += 128) {
        float x = sb[s], y = sb[s + NS], z = sb[s + 2 * NS];
        ssmp[s] = make_float4(x, y, z, fmaf(x, x, fmaf(y, y, z * z)));
    }
    __syncthreads();

    const int nA = n0 + tid, nB = nA + 128;
    const float* pb = pp + (size_t)b * 3 * NPTS;
    const float ax = pb[nA], ay = pb[nA + NPTS], az = pb[nA + 2 * NPTS];
    const float bx = pb[nB], by = pb[nB + NPTS], bz = pb[nB + 2 * NPTS];

    float ad0 = FLT_MAX, ad1 = FLT_MAX, ad2 = FLT_MAX;
    float bd0 = FLT_MAX, bd1 = FLT_MAX, bd2 = FLT_MAX;
    int   ai0 = 0, ai1 = 0, ai2 = 0, bi0 = 0, bi1 = 0, bi2 = 0;

    #pragma unroll 4
    for (int j = 0; j < NS; j++) {
        float4 q  = ssmp[j];
        float sA = fmaf(-2.0f, fmaf(ax, q.x, fmaf(ay, q.y, az * q.z)), q.w);
        float sB = fmaf(-2.0f, fmaf(bx, q.x, fmaf(by, q.y, bz * q.z)), q.w);
        if (sA < ad2) {
            if (sA < ad1) {
                ad2 = ad1; ai2 = ai1;
                if (sA < ad0) { ad1 = ad0; ai1 = ai0; ad0 = sA; ai0 = j; }
                else          { ad1 = sA; ai1 = j; }
            } else { ad2 = sA; ai2 = j; }
        }
        if (sB < bd2) {
            if (sB < bd1) {
                bd2 = bd1; bi2 = bi1;
                if (sB < bd0) { bd1 = bd0; bi1 = bi0; bd0 = sB; bi0 = j; }
                else          { bd1 = sB; bi1 = j; }
            } else { bd2 = sB; bi2 = j; }
        }
    }

    {
        const float p2 = fmaf(ax, ax, fmaf(ay, ay, az * az));
        float a0 = 1.0f / ((ad0 + p2) + 1e-8f);
        float a1 = 1.0f / ((ad1 + p2) + 1e-8f);
        float a2 = 1.0f / ((ad2 + p2) + 1e-8f);
        float inv = 1.0f / (a0 + a1 + a2);
        g_w[b * NPTS + nA] = make_float4(a0 * inv, a1 * inv, a2 * inv, 0.0f);
        g_i[b * NPTS + nA] = make_int4(ai0, ai1, ai2, 0);
    }
    {
        const float p2 = fmaf(bx, bx, fmaf(by, by, bz * bz));
        float a0 = 1.0f / ((bd0 + p2) + 1e-8f);
        float a1 = 1.0f / ((bd1 + p2) + 1e-8f);
        float a2 = 1.0f / ((bd2 + p2) + 1e-8f);
        float inv = 1.0f / (a0 + a1 + a2);
        g_w[b * NPTS + nB] = make_float4(a0 * inv, a1 * inv, a2 * inv, 0.0f);
        g_i[b * NPTS + nB] = make_int4(bi0, bi1, bi2, 0);
    }
}

// ---------------------------------------------------------------------------
// Kernel 3 (launch #3): interpolation -> g_BP1 rows 64..191 (half2 packed)
// ---------------------------------------------------------------------------
__global__ void __launch_bounds__(256) interp_kernel()
{
    __shared__ float  st[D2][33];
    __shared__ float4 sw[32];
    __shared__ int4   si[32];

    const int m0  = blockIdx.x * 32;
    const int b   = m0 / NPTS;
    const int tid = threadIdx.x;

    if (tid < 32) { sw[tid] = g_w[m0 + tid]; si[tid] = g_i[m0 + tid]; }
    __syncthreads();

    const float* fT = g_sfT + (size_t)b * NS * D2;
    #pragma unroll 8
    for (int p = 0; p < 32; p++) {
        float4 w = sw[p];
        int4   ii = si[p];
        float v = fmaf(w.x, __ldg(fT + (size_t)ii.x * D2 + tid),
                  fmaf(w.y, __ldg(fT + (size_t)ii.y * D2 + tid),
                       w.z * __ldg(fT + (size_t)ii.z * D2 + tid)));
        st[tid][p] = v;
    }
    __syncthreads();

    const int cpb = tid >> 3;
    const int j   = (tid & 7) << 2;
    #pragma unroll
    for (int r = 0; r < 4; r++) {
        int cp = r * 32 + cpb;
        uint32_t v[4];
        #pragma unroll
        for (int e = 0; e < 4; e++) {
            __half2 h = __floats2half2_rn(st[2 * cp][j + e], st[2 * cp + 1][j + e]);
            v[e] = *reinterpret_cast<uint32_t*>(&h);
        }
        *(uint4*)&g_BP1[(size_t)(64 + cp) * MTOT + m0 + j] = *(uint4*)v;
    }
}

// ---------------------------------------------------------------------------
// Shared MMA compute (As [m][kpair], Bs [kpair][n ^ (kp<<3)])
// ---------------------------------------------------------------------------
#define MMA_COMPUTE(ASBUF, BSBUF)                                             \
{                                                                             \
    uint32_t bf[4][2];                                                        \
    _Pragma("unroll")                                                         \
    for (int nt = 0; nt < 4; nt++) {                                          \
        int n = wn * 32 + nt * 8 + g;                                         \
        bf[nt][0] = (BSBUF)[t * 128 + (n ^ (t << 3))];                        \
        bf[nt][1] = (BSBUF)[(t + 4) * 128 + (n ^ ((t + 4) << 3))];            \
    }                                                                         \
    _Pragma("unroll")                                                         \
    for (int mt = 0; mt < 4; mt++) {                                          \
        int r = wm * 64 + mt * 16 + g;                                        \
        uint32_t ah[4];                                                       \
        ah[0] = (ASBUF)[r * 8 + t];                                           \
        ah[1] = (ASBUF)[(r + 8) * 8 + t];                                     \
        ah[2] = (ASBUF)[r * 8 + t + 4];                                       \
        ah[3] = (ASBUF)[(r + 8) * 8 + t + 4];                                 \
        _Pragma("unroll")                                                     \
        for (int nt = 0; nt < 4; nt++)                                        \
            mma16816(acc[mt][nt], ah, bf[nt]);                                \
    }                                                                         \
}

// gemm2 variant: BN1 + ReLU applied on B fragments (half2 hfma2/hmax2).
// kstep KI: fragment row t holds channels (2*(KI*8+t), +1); row t+4 likewise.
#define MMA_COMPUTE_BN(ASBUF, BSBUF, KI)                                      \
{                                                                             \
    const __half2 z2 = __float2half2_rn(0.0f);                                \
    __half2 sc0 = ((const __half2*)g_sc1h)[(KI) * 8 + t];                     \
    __half2 sh0 = ((const __half2*)g_sh1h)[(KI) * 8 + t];                     \
    __half2 sc1 = ((const __half2*)g_sc1h)[(KI) * 8 + t + 4];                 \
    __half2 sh1 = ((const __half2*)g_sh1h)[(KI) * 8 + t + 4];                 \
    uint32_t bf[4][2];                                                        \
    _Pragma("unroll")                                                         \
    for (int nt = 0; nt < 4; nt++) {                                          \
        int n = wn * 32 + nt * 8 + g;                                         \
        bf[nt][0] = (BSBUF)[t * 128 + (n ^ (t << 3))];                        \
        bf[nt][1] = (BSBUF)[(t + 4) * 128 + (n ^ ((t + 4) << 3))];            \
        __half2 h0 = *reinterpret_cast<__half2*>(&bf[nt][0]);                 \
        __half2 h1 = *reinterpret_cast<__half2*>(&bf[nt][1]);                 \
        h0 = __hmax2(__hfma2(h0, sc0, sh0), z2);                              \
        h1 = __hmax2(__hfma2(h1, sc1, sh1), z2);                              \
        bf[nt][0] = *reinterpret_cast<uint32_t*>(&h0);                        \
        bf[nt][1] = *reinterpret_cast<uint32_t*>(&h1);                        \
    }                                                                         \
    _Pragma("unroll")                                                         \
    for (int mt = 0; mt < 4; mt++) {                                          \
        int r = wm * 64 + mt * 16 + g;                                        \
        uint32_t ah[4];                                                       \
        ah[0] = (ASBUF)[r * 8 + t];                                           \
        ah[1] = (ASBUF)[(r + 8) * 8 + t];                                     \
        ah[2] = (ASBUF)[r * 8 + t + 4];                                       \
        ah[3] = (ASBUF)[(r + 8) * 8 + t + 4];                                 \
        _Pragma("unroll")                                                     \
        for (int nt = 0; nt < 4; nt++)                                        \
            mma16816(acc[mt][nt], ah, bf[nt]);                                \
    }                                                                         \
}

// BN partial-stat emission (sum/sumsq from fp32 accumulators)
#define BN_PARTIALS(PSUM, PSQ, SS_SMEM, SQ_SMEM)                              \
{                                                                             \
    __syncthreads();                                                          \
    float* Ssum = (SS_SMEM);                                                  \
    float* Ssq  = (SQ_SMEM);                                                  \
    const int ci = wn * 4 + t;                                                \
    _Pragma("unroll")                                                         \
    for (int mt = 0; mt < 4; mt++) {                                          \
        int r0 = wm * 64 + mt * 16 + g;                                       \
        float s0 = 0.f, q0 = 0.f, s1 = 0.f, q1 = 0.f;                         \
        _Pragma("unroll")                                                     \
        for (int nt = 0; nt < 4; nt++) {                                      \
            float e0 = acc[mt][nt][0], e1 = acc[mt][nt][1];                   \
            float e2 = acc[mt][nt][2], e3 = acc[mt][nt][3];                   \
            s0 += e0 + e1;  q0 += e0 * e0 + e1 * e1;                          \
            s1 += e2 + e3;  q1 += e2 * e2 + e3 * e3;                          \
        }                                                                     \
        Ssum[ci * 128 + r0]     = s0;  Ssq[ci * 128 + r0]     = q0;           \
        Ssum[ci * 128 + r0 + 8] = s1;  Ssq[ci * 128 + r0 + 8] = q1;           \
    }                                                                         \
    __syncthreads();                                                          \
    if (tid < 128) {                                                          \
        float s = 0.f;                                                        \
        _Pragma("unroll")                                                     \
        for (int c = 0; c < 16; c++) s += Ssum[c * 128 + tid];                \
        (PSUM)[(size_t)(i0 + tid) * GRIDX + blockIdx.x] = s;                  \
    } else {                                                                  \
        int r = tid - 128;                                                    \
        float q = 0.f;                                                        \
        _Pragma("unroll")                                                     \
        for (int c = 0; c < 16; c++) q += Ssq[c * 128 + r];                   \
        (PSQ)[(size_t)(i0 + r) * GRIDX + blockIdx.x] = q;                     \
    }                                                                         \
}

// ---------------------------------------------------------------------------
// Kernel 4 (launch #4 — PROFILED): GEMM1 — unchanged from R14 (69.7us).
//   Epilogue packs h1 as raw fp16 k-pairs into g_BP2 + BN1 partials.
// ---------------------------------------------------------------------------
__global__ void __launch_bounds__(256) gemm1_kernel()
{
    __shared__ uint32_t As[4][128 * 8];
    __shared__ uint32_t Bs[4][8 * 128];

    const int tid  = threadIdx.x;
    const int lane = tid & 31;
    const int wid  = tid >> 5;
    const int wm   = wid >> 2;
    const int wn   = wid & 3;
    const int g    = lane >> 2;
    const int t    = lane & 3;

    const int j0 = blockIdx.x * 128;
    const int i0 = blockIdx.y * 128;

    const int arow = tid >> 1;
    const int akh  = tid & 1;
    const int brp  = tid >> 5;
    const int bc0  = lane * 4;

    const uint32_t a_dst0 = (uint32_t)__cvta_generic_to_shared(&As[0][arow * 8 + akh * 4]);
    const uint32_t b_dst0 = (uint32_t)__cvta_generic_to_shared(&Bs[0][brp * 128 + (bc0 ^ (brp << 3))]);
    const __half*   a_src0 = g_W1h + (size_t)(i0 + arow) * C1 + akh * 8;
    const uint32_t* b_src0 = g_BP1 + (size_t)brp * MTOT + j0 + bc0;

    float acc[4][4][4];
    #pragma unroll
    for (int mt = 0; mt < 4; mt++)
        #pragma unroll
        for (int nt = 0; nt < 4; nt++)
            #pragma unroll
            for (int e = 0; e < 4; e++) acc[mt][nt][e] = 0.0f;

    #define G1_ISSUE(step)                                                    \
    {                                                                         \
        int s_ = (step) & 3;                                                  \
        cp_async16(a_dst0 + s_ * 4096, a_src0 + (step) * 16);                 \
        cp_async16(b_dst0 + s_ * 4096, b_src0 + (size_t)(step) * 8 * MTOT);   \
        CP_COMMIT();                                                          \
    }

    G1_ISSUE(0); G1_ISSUE(1); G1_ISSUE(2);

    #pragma unroll 1
    for (int i = 0; i < 21; i++) {
        CP_WAIT(2);
        __syncthreads();
        G1_ISSUE(i + 3);
        MMA_COMPUTE(As[i & 3], Bs[i & 3]);
    }
    CP_WAIT(2); __syncthreads(); MMA_COMPUTE(As[21 & 3], Bs[21 & 3]);
    CP_WAIT(1); __syncthreads(); MMA_COMPUTE(As[22 & 3], Bs[22 & 3]);
    CP_WAIT(0); __syncthreads(); MMA_COMPUTE(As[23 & 3], Bs[23 & 3]);

    // ---- epilogue: pack h1 -> raw fp16 k-pairs in g_BP2 ----
    #pragma unroll
    for (int mt = 0; mt < 4; mt++) {
        #pragma unroll
        for (int nt = 0; nt < 4; nt++) {
            float v0 = acc[mt][nt][0], v1 = acc[mt][nt][1];
            float v2 = acc[mt][nt][2], v3 = acc[mt][nt][3];
            float p0 = __shfl_down_sync(0xFFFFFFFFu, v0, 4);
            float p1 = __shfl_down_sync(0xFFFFFFFFu, v1, 4);
            float p2 = __shfl_down_sync(0xFFFFFFFFu, v2, 4);
            float p3 = __shfl_down_sync(0xFFFFFFFFu, v3, 4);
            if (!(g & 1)) {
                int r   = wm * 64 + mt * 16 + g;
                int cp0 = (i0 + r) >> 1;
                int col = j0 + wn * 32 + nt * 8 + 2 * t;
                __half2 h0 = __floats2half2_rn(v0, p0);
                __half2 h1 = __floats2half2_rn(v1, p1);
                uint2 w0 = make_uint2(*(uint32_t*)&h0, *(uint32_t*)&h1);
                *(uint2*)&g_BP2[(size_t)cp0 * MTOT + col] = w0;
                __half2 h2 = __floats2half2_rn(v2, p2);
                __half2 h3 = __floats2half2_rn(v3, p3);
                uint2 w1 = make_uint2(*(uint32_t*)&h2, *(uint32_t*)&h3);
                *(uint2*)&g_BP2[(size_t)(cp0 + 4) * MTOT + col] = w1;
            }
        }
    }

    BN_PARTIALS(g_psA, g_pqA, (float*)As, (float*)Bs);
    #undef G1_ISSUE
}

// ---------------------------------------------------------------------------
// Kernel 5: GEMM2 — pure-copy cp.async loaders; BN1+ReLU fused on B FRAGMENTS.
//   H2 = W2 @ relu(BN1(H1)); raw fp16 h1 read from g_BP2.
// ---------------------------------------------------------------------------
__global__ void __launch_bounds__(256) gemm2_kernel()
{
    __shared__ uint32_t As[4][128 * 8];
    __shared__ uint32_t Bs[4][8 * 128];

    const int tid  = threadIdx.x;
    const int lane = tid & 31;
    const int wid  = tid >> 5;
    const int wm   = wid >> 2;
    const int wn   = wid & 3;
    const int g    = lane >> 2;
    const int t    = lane & 3;

    const int j0 = blockIdx.x * 128;
    const int i0 = 0;

    const int arow = tid >> 1;
    const int akh  = tid & 1;
    const int brp  = tid >> 5;
    const int bc0  = lane * 4;

    const uint32_t a_dst0 = (uint32_t)__cvta_generic_to_shared(&As[0][arow * 8 + akh * 4]);
    const uint32_t b_dst0 = (uint32_t)__cvta_generic_to_shared(&Bs[0][brp * 128 + (bc0 ^ (brp << 3))]);
    const __half*   a_src0 = g_W2h + (size_t)arow * C2 + akh * 8;
    const uint32_t* b_src0 = g_BP2 + (size_t)brp * MTOT + j0 + bc0;

    float acc[4][4][4];
    #pragma unroll
    for (int mt = 0; mt < 4; mt++)
        #pragma unroll
        for (int nt = 0; nt < 4; nt++)
            #pragma unroll
            for (int e = 0; e < 4; e++) acc[mt][nt][e] = 0.0f;

    #define G2_ISSUE(step)                                                    \
    {                                                                         \
        int s_ = (step) & 3;                                                  \
        cp_async16(a_dst0 + s_ * 4096, a_src0 + (step) * 16);                 \
        cp_async16(b_dst0 + s_ * 4096, b_src0 + (size_t)(step) * 8 * MTOT);   \
        CP_COMMIT();                                                          \
    }

    G2_ISSUE(0); G2_ISSUE(1); G2_ISSUE(2);

    #pragma unroll 1
    for (int i = 0; i < 13; i++) {
        CP_WAIT(2);
        __syncthreads();
        G2_ISSUE(i + 3);
        MMA_COMPUTE_BN(As[i & 3], Bs[i & 3], i);
    }
    CP_WAIT(2); __syncthreads(); MMA_COMPUTE_BN(As[13 & 3], Bs[13 & 3], 13);
    CP_WAIT(1); __syncthreads(); MMA_COMPUTE_BN(As[14 & 3], Bs[14 & 3], 14);
    CP_WAIT(0); __syncthreads(); MMA_COMPUTE_BN(As[15 & 3], Bs[15 & 3], 15);

    // store h2 fp32 + BN2 partials
    #pragma unroll
    for (int mt = 0; mt < 4; mt++) {
        #pragma unroll
        for (int nt = 0; nt < 4; nt++) {
            int row = wm * 64 + mt * 16 + g;
            int col = j0 + wn * 32 + nt * 8 + 2 * t;
            *(float2*)&g_h2[(size_t)row * MTOT + col] =
                make_float2(acc[mt][nt][0], acc[mt][nt][1]);
            *(float2*)&g_h2[(size_t)(row + 8) * MTOT + col] =
                make_float2(acc[mt][nt][2], acc[mt][nt][3]);
        }
    }

    BN_PARTIALS(g_psB, g_pqB, (float*)As, (float*)Bs);
    #undef G2_ISSUE
}

// ---------------------------------------------------------------------------
// Kernel 6: reduce per-block partials -> per-channel (scale, shift).
//   which==1 additionally emits fp16 scale/shift for the fragment fuse.
// ---------------------------------------------------------------------------
__global__ void __launch_bounds__(256) bn_reduce_kernel(
    const float* __restrict__ g, const float* __restrict__ beta, int which)
{
    const int c   = blockIdx.x;
    const int tid = threadIdx.x;
    const float* ps = (which == 1) ? g_psA : g_psB;
    const float* pq = (which == 1) ? g_pqA : g_pqB;

    double s = (double)ps[(size_t)c * GRIDX + tid] + (double)ps[(size_t)c * GRIDX + tid + 256];
    double q = (double)pq[(size_t)c * GRIDX + tid] + (double)pq[(size_t)c * GRIDX + tid + 256];

    __shared__ double r1[256], r2[256];
    r1[tid] = s;  r2[tid] = q;
    __syncthreads();
    for (int o = 128; o > 0; o >>= 1) {
        if (tid < o) { r1[tid] += r1[tid + o]; r2[tid] += r2[tid + o]; }
        __syncthreads();
    }
    if (tid == 0) {
        double mean = r1[0] / (double)MTOT;
        double var  = r2[0] / (double)MTOT - mean * mean;
        double rs   = 1.0 / sqrt(var + 1e-5);
        float scale = (float)((double)g[c] * rs);
        float shift = (float)((double)beta[c] - mean * (double)g[c] * rs);
        if (which == 1) {
            g_ss1[c]  = make_float2(scale, shift);
            g_sc1h[c] = __float2half_rn(scale);
            g_sh1h[c] = __float2half_rn(shift);
        } else {
            g_ss2[c] = make_float2(scale, shift);
        }
    }
}

// ---------------------------------------------------------------------------
// Kernel 7: final BN2 + ReLU + layout transform [c][b*N+n] -> [b][c][n]
// ---------------------------------------------------------------------------
__global__ void __launch_bounds__(256) bn_out_kernel(float* __restrict__ out)
{
    size_t f = (size_t)blockIdx.x * blockDim.x + threadIdx.x;
    size_t e = f * 4;
    int c = (int)(e / MTOT);
    int m = (int)(e % MTOT);
    int b = m / NPTS;
    int n = m % NPTS;

    float4 v = ((const float4*)g_h2)[f];
    float2 ss = g_ss2[c];
    v.x = fmaxf(fmaf(v.x, ss.x, ss.y), 0.0f);
    v.y = fmaxf(fmaf(v.y, ss.x, ss.y), 0.0f);
    v.z = fmaxf(fmaf(v.z, ss.x, ss.y), 0.0f);
    v.w = fmaxf(fmaf(v.w, ss.x, ss.y), 0.0f);
    *(float4*)(out + ((size_t)b * C3 + c) * NPTS + n) = v;
}

// ---------------------------------------------------------------------------
// Launcher — gemm1 stays the 4th launch (ncu captures launch #4)
// ---------------------------------------------------------------------------
extern "C" void kernel_launch(void* const* d_in, const int* in_sizes, int n_in,
                              void* d_out, int out_size)
{
    const float* pp    = (const float*)d_in[0];
    const float* spp   = (const float*)d_in[1];
    const float* skip  = (const float*)d_in[2];
    const float* sfeat = (const float*)d_in[3];
    const float* W1    = (const float*)d_in[4];
    // d_in[5] = b1 (cancels inside BN)
    const float* g1    = (const float*)d_in[6];
    const float* be1   = (const float*)d_in[7];
    const float* W2    = (const float*)d_in[8];
    // d_in[9] = b2 (cancels inside BN)
    const float* g2    = (const float*)d_in[10];
    const float* be2   = (const float*)d_in[11];
    float* out = (float*)d_out;

    // #1: fused preprocessing
    prep_all_kernel<<<PREP_TOTAL, 256>>>(W1, W2, skip, sfeat);

    // #2: 3-NN
    knn_kernel<<<B_ * (NPTS / 256), 128>>>(pp, spp);

    // #3: interpolation -> g_BP1 rows 64..191
    interp_kernel<<<MTOT / 32, 256>>>();

    // #4 (PROFILED): GEMM1 -> packed raw fp16 h1 + BN1 partials
    {
        dim3 grid(GRIDX, C2 / 128);
        gemm1_kernel<<<grid, 256>>>();
    }
    bn_reduce_kernel<<<C2, 256>>>(g1, be1, 1);

    // #6: GEMM2 (BN1+ReLU fused on fragments) -> h2 + BN2 partials
    gemm2_kernel<<<GRIDX, 256>>>();
    bn_reduce_kernel<<<C3, 256>>>(g2, be2, 2);

    // #8: BN2 apply + ReLU + transpose to [B,128,N]
    bn_out_kernel<<<(C3 * MTOT / 4) / 256, 256>>>(out);
}